// round 15
// baseline (speedup 1.0000x reference)
#include <cuda_runtime.h>
#include <cuda_bf16.h>

#define NN 50000
#define EE 500000
#define HD 128
#define NLAY 4
#define NG 64
#define NB 196
#define G128 391

// interleaved split-weight matrices: 20 x [128 n][128 words]
// word[kw*2] = bf16x2 hi (k=2kw,2kw+1); word[kw*2+1] = bf16x2 lo
// idx 0..7 = msg W1a/W1b ; 8..11 = U1a[l] ; 12..15 = W2U[l] ; 16..19 = U2[l]
__device__ __align__(16) unsigned d_wi[20 * 16384];

// pre-split activations: [row][64 u64], u64 = {hi bf16x2 (lo32), lo bf16x2 (hi32)}
__device__ __align__(16) unsigned long long d_hsp[NN * 64];
__device__ __align__(16) unsigned long long d_Ysp[NN * 64];
__device__ __align__(16) unsigned long long d_Tsp[NN * 64];

__device__ __align__(16) float d_h[NN * HD];
__device__ __align__(16) float d_P1[NN * HD];
__device__ __align__(16) float d_P2[NN * HD];
__device__ __align__(16) float d_degf[NN];
__device__ __align__(16) float d_W2U[NLAY * HD * HD];
__device__ __align__(16) float d_cvec[NLAY * HD];
__device__ __align__(16) float d_pooled[NG * HD];
__device__ __align__(16) float d_cnt[NG];
__device__ __align__(16) int   d_rowptr[NN + 1];
__device__ __align__(16) int   d_cursor[NN];
__device__ __align__(16) int   d_bsum[256];
__device__ __align__(16) int2  d_epack[EE];

// ---------------- helpers -------------------------------------------------------
__device__ __forceinline__ unsigned smem_u32(const void* p) {
    unsigned r;
    asm("{ .reg .u64 t; cvta.to.shared.u64 t, %1; cvt.u32.u64 %0, t; }"
        : "=r"(r) : "l"(p));
    return r;
}
__device__ __forceinline__ void cp16(unsigned saddr, const void* g) {
    asm volatile("cp.async.cg.shared.global [%0], [%1], 16;" :: "r"(saddr), "l"(g));
}
__device__ __forceinline__ void cp_commit_wait() {
    asm volatile("cp.async.commit_group;");
    asm volatile("cp.async.wait_group 0;");
}

__device__ __forceinline__ void mma_bf16(float c[4], const unsigned a[4],
                                         unsigned b0, unsigned b1) {
    asm volatile(
        "mma.sync.aligned.m16n8k16.row.col.f32.bf16.bf16.f32 "
        "{%0,%1,%2,%3}, {%4,%5,%6,%7}, {%8,%9}, {%0,%1,%2,%3};"
        : "+f"(c[0]), "+f"(c[1]), "+f"(c[2]), "+f"(c[3])
        : "r"(a[0]), "r"(a[1]), "r"(a[2]), "r"(a[3]), "r"(b0), "r"(b1));
}

// fast split: packed cvt + reconstruct-hi + packed cvt of residual
__device__ __forceinline__ void split2(float2 f, unsigned& hi, unsigned& lo) {
    unsigned h;
    asm("cvt.rn.bf16x2.f32 %0, %1, %2;" : "=r"(h) : "f"(f.y), "f"(f.x));
    float h0 = __uint_as_float(h << 16);
    float h1 = __uint_as_float(h & 0xFFFF0000u);
    unsigned l;
    float ry = f.y - h1, rx = f.x - h0;
    asm("cvt.rn.bf16x2.f32 %0, %1, %2;" : "=r"(l) : "f"(ry), "f"(rx));
    hi = h; lo = l;
}
__device__ __forceinline__ unsigned long long sp2(float a, float b) {
    unsigned h, l;
    split2(make_float2(a, b), h, l);
    return ((unsigned long long)l << 32) | h;
}

// ---------------- HMMA building blocks ------------------------------------------
#define BROW 136
#define BTILE 69632

__device__ __forceinline__ void stageB(unsigned sb, const unsigned* __restrict__ wi,
                                       int tid, int nthr) {
    for (int c = tid; c < 4096; c += nthr) {
        int n = c >> 5;
        int c4 = c & 31;
        cp16(sb + (unsigned)((n * BROW + c4 * 4) * 4), wi + n * 128 + c4 * 4);
    }
}

// pre-split A fragment load: 4 LDG.64, zero ALU
__device__ __forceinline__ void loadA_sp(const unsigned long long* __restrict__ Asp,
                                         int cr0, int cr1, int k0, int tig,
                                         unsigned ahi[4], unsigned alo[4]) {
    int kw = (k0 >> 1) + tig;
    unsigned long long q0 = Asp[cr0 * 64 + kw];
    unsigned long long q1 = Asp[cr1 * 64 + kw];
    unsigned long long q2 = Asp[cr0 * 64 + kw + 4];
    unsigned long long q3 = Asp[cr1 * 64 + kw + 4];
    ahi[0] = (unsigned)q0; alo[0] = (unsigned)(q0 >> 32);
    ahi[1] = (unsigned)q1; alo[1] = (unsigned)(q1 >> 32);
    ahi[2] = (unsigned)q2; alo[2] = (unsigned)(q2 >> 32);
    ahi[3] = (unsigned)q3; alo[3] = (unsigned)(q3 >> 32);
}

__device__ __forceinline__ void mma3_tiles(float acc[16][4], const char* __restrict__ smB,
                                           int k0, int g, int tig,
                                           const unsigned ahi[4], const unsigned alo[4]) {
    int kwofs = ((k0 >> 1) + tig) * 2;
#pragma unroll
    for (int t = 0; t < 16; t++) {
        int n = t * 8 + g;
        const char* base = smB + (n * BROW + kwofs) * 4;
        unsigned long long q0 = *(const unsigned long long*)(base);
        unsigned long long q1 = *(const unsigned long long*)(base + 32);
        unsigned bh0 = (unsigned)q0, bl0 = (unsigned)(q0 >> 32);
        unsigned bh1 = (unsigned)q1, bl1 = (unsigned)(q1 >> 32);
        mma_bf16(acc[t], ahi, bh0, bh1);
        mma_bf16(acc[t], ahi, bl0, bl1);
        mma_bf16(acc[t], alo, bh0, bh1);
    }
}

// ---------------- p12: P1/P2 message GEMM (16x128 warp tile) --------------------
// 256 thr, 8 warps x 16 rows = 128 rows. Blocks [0,391) -> P1, [391,782) -> P2.
__global__ void __launch_bounds__(256) p12_tc(
    const unsigned long long* __restrict__ Asp,
    const unsigned* __restrict__ wiPair,
    const float* __restrict__ bias,
    float* __restrict__ O1, float* __restrict__ O2) {
    extern __shared__ char smc[];
    unsigned sb = smem_u32(smc);
    int tid = threadIdx.x;
    int wid = tid >> 5, lane = tid & 31;
    int g = lane >> 2, tig = lane & 3;

    int pr = (blockIdx.x >= G128) ? 1 : 0;
    int blk = blockIdx.x - pr * G128;

    stageB(sb, wiPair + pr * 16384, tid, 256);
    cp_commit_wait();
    __syncthreads();

    int rowbase = blk * 128 + wid * 16;
    int r0 = rowbase + g, r1 = rowbase + g + 8;
    int cr0 = (r0 < NN) ? r0 : (NN - 1);
    int cr1 = (r1 < NN) ? r1 : (NN - 1);

    float acc[16][4];
#pragma unroll
    for (int i = 0; i < 16; i++)
#pragma unroll
        for (int j = 0; j < 4; j++) acc[i][j] = 0.0f;

#pragma unroll
    for (int ks = 0; ks < 8; ks++) {
        int k0 = ks * 16;
        unsigned ahi[4], alo[4];
        loadA_sp(Asp, cr0, cr1, k0, tig, ahi, alo);
        mma3_tiles(acc, smc, k0, g, tig, ahi, alo);
    }

    float* Op = pr ? O2 : O1;
#pragma unroll
    for (int t = 0; t < 16; t++) {
        int col = t * 8 + tig * 2;
        float2 bv = make_float2(0.f, 0.f);
        if (pr == 0) bv = *(const float2*)&bias[col];
        float2 v0 = make_float2(acc[t][0] + bv.x, acc[t][1] + bv.y);
        float2 v1 = make_float2(acc[t][2] + bv.x, acc[t][3] + bv.y);
        if (r0 < NN) *(float2*)(Op + r0 * HD + col) = v0;
        if (r1 < NN) *(float2*)(Op + r1 * HD + col) = v1;
    }
}

// ---------------- upd2: Tsp = split(relu(h@U1a + Y@W2U + deg*cvec + bias)) ------
__global__ void __launch_bounds__(256) upd2_tc(
    const unsigned long long* __restrict__ A0sp,
    const unsigned long long* __restrict__ A1sp,
    const unsigned* __restrict__ wi0, const unsigned* __restrict__ wi1,
    const float* __restrict__ bias, const float* __restrict__ degf,
    const float* __restrict__ cvec, unsigned long long* __restrict__ Tsp) {
    extern __shared__ char smc[];
    unsigned sb = smem_u32(smc);
    int tid = threadIdx.x;
    int wid = tid >> 5, lane = tid & 31;
    int g = lane >> 2, tig = lane & 3;

    stageB(sb, wi0, tid, 256);
    cp_commit_wait();
    __syncthreads();

    int rowbase = blockIdx.x * 128 + wid * 16;
    int r0 = rowbase + g, r1 = rowbase + g + 8;
    int cr0 = (r0 < NN) ? r0 : (NN - 1);
    int cr1 = (r1 < NN) ? r1 : (NN - 1);

    float acc[16][4];
#pragma unroll
    for (int i = 0; i < 16; i++)
#pragma unroll
        for (int j = 0; j < 4; j++) acc[i][j] = 0.0f;

#pragma unroll
    for (int ks = 0; ks < 8; ks++) {
        int k0 = ks * 16;
        unsigned ahi[4], alo[4];
        loadA_sp(A0sp, cr0, cr1, k0, tig, ahi, alo);
        mma3_tiles(acc, smc, k0, g, tig, ahi, alo);
    }
    __syncthreads();
    stageB(sb, wi1, tid, 256);
    cp_commit_wait();
    __syncthreads();
#pragma unroll
    for (int ks = 0; ks < 8; ks++) {
        int k0 = ks * 16;
        unsigned ahi[4], alo[4];
        loadA_sp(A1sp, cr0, cr1, k0, tig, ahi, alo);
        mma3_tiles(acc, smc, k0, g, tig, ahi, alo);
    }

    float dg0 = degf[cr0], dg1 = degf[cr1];
#pragma unroll
    for (int t = 0; t < 16; t++) {
        int col = t * 8 + tig * 2;
        float2 bv = *(const float2*)&bias[col];
        float2 cv = *(const float2*)&cvec[col];
        float v0x = fmaxf(acc[t][0] + dg0 * cv.x + bv.x, 0.0f);
        float v0y = fmaxf(acc[t][1] + dg0 * cv.y + bv.y, 0.0f);
        float v1x = fmaxf(acc[t][2] + dg1 * cv.x + bv.x, 0.0f);
        float v1y = fmaxf(acc[t][3] + dg1 * cv.y + bv.y, 0.0f);
        if (r0 < NN) Tsp[r0 * 64 + (col >> 1)] = sp2(v0x, v0y);
        if (r1 < NN) Tsp[r1 * 64 + (col >> 1)] = sp2(v1x, v1y);
    }
}

// ---------------- upd3: h = (res? h:0) + relu(LN(T@U2 + bias)); emits h + hsp ---
__global__ void __launch_bounds__(256) upd3_tc(
    const unsigned long long* __restrict__ Asp,
    const unsigned* __restrict__ wiU,
    const float* __restrict__ bias,
    const float* __restrict__ lng, const float* __restrict__ lnb,
    int addres, float* __restrict__ Out, unsigned long long* __restrict__ hsp) {
    extern __shared__ char smc[];
    unsigned sb = smem_u32(smc);
    int tid = threadIdx.x;
    int wid = tid >> 5, lane = tid & 31;
    int g = lane >> 2, tig = lane & 3;

    stageB(sb, wiU, tid, 256);
    cp_commit_wait();
    __syncthreads();

    int rowbase = blockIdx.x * 128 + wid * 16;
    int r0 = rowbase + g, r1 = rowbase + g + 8;
    int cr0 = (r0 < NN) ? r0 : (NN - 1);
    int cr1 = (r1 < NN) ? r1 : (NN - 1);

    float acc[16][4];
#pragma unroll
    for (int i = 0; i < 16; i++)
#pragma unroll
        for (int j = 0; j < 4; j++) acc[i][j] = 0.0f;

#pragma unroll
    for (int ks = 0; ks < 8; ks++) {
        int k0 = ks * 16;
        unsigned ahi[4], alo[4];
        loadA_sp(Asp, cr0, cr1, k0, tig, ahi, alo);
        mma3_tiles(acc, smc, k0, g, tig, ahi, alo);
    }

    float s0 = 0.f, sq0 = 0.f, s1 = 0.f, sq1 = 0.f;
#pragma unroll
    for (int t = 0; t < 16; t++) {
        int col = t * 8 + tig * 2;
        float2 bv = *(const float2*)&bias[col];
        acc[t][0] += bv.x; acc[t][1] += bv.y;
        acc[t][2] += bv.x; acc[t][3] += bv.y;
        s0 += acc[t][0] + acc[t][1];
        sq0 += acc[t][0] * acc[t][0] + acc[t][1] * acc[t][1];
        s1 += acc[t][2] + acc[t][3];
        sq1 += acc[t][2] * acc[t][2] + acc[t][3] * acc[t][3];
    }
#pragma unroll
    for (int off = 1; off <= 2; off <<= 1) {
        s0 += __shfl_xor_sync(0xffffffffu, s0, off);
        sq0 += __shfl_xor_sync(0xffffffffu, sq0, off);
        s1 += __shfl_xor_sync(0xffffffffu, s1, off);
        sq1 += __shfl_xor_sync(0xffffffffu, sq1, off);
    }
    float mu0 = s0 * (1.0f / HD);
    float mu1 = s1 * (1.0f / HD);
    float rstd0 = rsqrtf(sq0 * (1.0f / HD) - mu0 * mu0 + 1e-5f);
    float rstd1 = rsqrtf(sq1 * (1.0f / HD) - mu1 * mu1 + 1e-5f);

#pragma unroll
    for (int t = 0; t < 16; t++) {
        int col = t * 8 + tig * 2;
        float2 gv = *(const float2*)&lng[col];
        float2 lv = *(const float2*)&lnb[col];
        float2 v0, v1;
        v0.x = fmaxf((acc[t][0] - mu0) * rstd0 * gv.x + lv.x, 0.0f);
        v0.y = fmaxf((acc[t][1] - mu0) * rstd0 * gv.y + lv.y, 0.0f);
        v1.x = fmaxf((acc[t][2] - mu1) * rstd1 * gv.x + lv.x, 0.0f);
        v1.y = fmaxf((acc[t][3] - mu1) * rstd1 * gv.y + lv.y, 0.0f);
        if (r0 < NN) {
            if (addres) {
                float2 hv = *(const float2*)(Out + r0 * HD + col);
                v0.x += hv.x; v0.y += hv.y;
            }
            *(float2*)(Out + r0 * HD + col) = v0;
            hsp[r0 * 64 + (col >> 1)] = sp2(v0.x, v0.y);
        }
        if (r1 < NN) {
            if (addres) {
                float2 hv = *(const float2*)(Out + r1 * HD + col);
                v1.x += hv.x; v1.y += hv.y;
            }
            *(float2*)(Out + r1 * HD + col) = v1;
            hsp[r1 * 64 + (col >> 1)] = sp2(v1.x, v1.y);
        }
    }
}

// ---------------- h f32 -> pre-split (after encoder) ----------------------------
__global__ void h2sp_k(const float* __restrict__ h, unsigned long long* __restrict__ hsp) {
    int i = blockIdx.x * 256 + threadIdx.x;
    if (i < NN * 64) {
        float2 f = ((const float2*)h)[i];
        hsp[i] = sp2(f.x, f.y);
    }
}

// ---------------- weight transpose + split + interleave -------------------------
__device__ __forceinline__ void split_store(unsigned* __restrict__ dst,
                                            int m, int n, int kw,
                                            float v0, float v1) {
    __nv_bfloat16 h0 = __float2bfloat16(v0), h1 = __float2bfloat16(v1);
    __nv_bfloat16 l0 = __float2bfloat16(v0 - __bfloat162float(h0));
    __nv_bfloat16 l1 = __float2bfloat16(v1 - __bfloat162float(h1));
    dst[m * 16384 + n * 128 + kw * 2] =
        ((unsigned)__bfloat16_as_ushort(h1) << 16) | __bfloat16_as_ushort(h0);
    dst[m * 16384 + n * 128 + kw * 2 + 1] =
        ((unsigned)__bfloat16_as_ushort(l1) << 16) | __bfloat16_as_ushort(l0);
}

__global__ void split_msg(const float* __restrict__ msg_w1, unsigned* __restrict__ wi) {
    int n = blockIdx.x, m = blockIdx.y, kw = threadIdx.x;
    int l = m >> 1, part = m & 1;
    const float* W = msg_w1 + l * 257 * HD + part * 128 * HD;
    split_store(wi, m, n, kw, W[(2 * kw) * HD + n], W[(2 * kw + 1) * HD + n]);
}

__global__ void split_upd(const float* __restrict__ upd_w1,
                          const float* __restrict__ W2U,
                          const float* __restrict__ upd_w2,
                          unsigned* __restrict__ wi) {
    int n = blockIdx.x, m2 = blockIdx.y, kw = threadIdx.x;
    const float* W;
    if (m2 < 4)       W = upd_w1 + m2 * 256 * HD;
    else if (m2 < 8)  W = W2U + (m2 - 4) * HD * HD;
    else              W = upd_w2 + (m2 - 8) * HD * HD;
    split_store(wi, 8 + m2, n, kw, W[(2 * kw) * HD + n], W[(2 * kw + 1) * HD + n]);
}

// ---------------- tiny utility kernels ------------------------------------------
__global__ void zero_k(float* __restrict__ p, int n) {
    int i = blockIdx.x * blockDim.x + threadIdx.x;
    if (i < n) p[i] = 0.0f;
}
__global__ void zero_int(int* __restrict__ p, int n) {
    int i = blockIdx.x * blockDim.x + threadIdx.x;
    if (i < n) p[i] = 0;
}

// ---------------- CSR build ------------------------------------------------------
__global__ void count_k(const int* __restrict__ ei, int* __restrict__ deg) {
    int e = blockIdx.x * blockDim.x + threadIdx.x;
    if (e < EE) atomicAdd(&deg[ei[EE + e]], 1);
}

__global__ void scan_part(const int* __restrict__ deg, int* __restrict__ rowptr,
                          int* __restrict__ bsum) {
    __shared__ int s[256];
    int tid = threadIdx.x;
    int i = blockIdx.x * 256 + tid;
    int v = (i < NN) ? deg[i] : 0;
    s[tid] = v;
    __syncthreads();
#pragma unroll
    for (int off = 1; off < 256; off <<= 1) {
        int t = (tid >= off) ? s[tid - off] : 0;
        __syncthreads();
        s[tid] += t;
        __syncthreads();
    }
    if (i < NN) rowptr[i] = s[tid] - v;
    if (tid == 255) bsum[blockIdx.x] = s[255];
}

__global__ void scan_bsum(int* __restrict__ bsum) {
    __shared__ int s[256];
    int tid = threadIdx.x;
    int v = (tid < NB) ? bsum[tid] : 0;
    s[tid] = v;
    __syncthreads();
#pragma unroll
    for (int off = 1; off < 256; off <<= 1) {
        int t = (tid >= off) ? s[tid - off] : 0;
        __syncthreads();
        s[tid] += t;
        __syncthreads();
    }
    if (tid < NB) bsum[tid] = s[tid] - v;
}

__global__ void add_off(int* __restrict__ rowptr, const int* __restrict__ bsum,
                        int* __restrict__ cursor) {
    int i = blockIdx.x * 256 + threadIdx.x;
    if (i < NN) {
        int r = rowptr[i] + bsum[blockIdx.x];
        rowptr[i] = r;
        cursor[i] = r;
    }
    if (i == 0) rowptr[NN] = EE;
}

__global__ void degf_k(const int* __restrict__ rowptr, float* __restrict__ degf) {
    int i = blockIdx.x * blockDim.x + threadIdx.x;
    if (i < NN) degf[i] = (float)(rowptr[i + 1] - rowptr[i]);
}

__global__ void scatter_k(const int* __restrict__ ei,
                          const float* __restrict__ pos,
                          int* __restrict__ cursor,
                          int2* __restrict__ epack) {
    int e = blockIdx.x * blockDim.x + threadIdx.x;
    if (e >= EE) return;
    int s = ei[e];
    int t = ei[EE + e];
    float dx = pos[t * 3 + 0] - pos[s * 3 + 0];
    float dy = pos[t * 3 + 1] - pos[s * 3 + 1];
    float dz = pos[t * 3 + 2] - pos[s * 3 + 2];
    float dd = sqrtf(dx * dx + dy * dy + dz * dz);
    int p = atomicAdd(&cursor[t], 1);
    epack[p] = make_int2(s, __float_as_int(dd));
}

// ---------------- encoder --------------------------------------------------------
__global__ void encoder_k(const float* __restrict__ x,
                          const float* __restrict__ w,
                          const float* __restrict__ b,
                          float* __restrict__ h) {
    __shared__ float ws[15 * HD];
    __shared__ float xs[16 * 15];
    __shared__ float bs[HD];
    int c = threadIdx.x;
    for (int i = c; i < 15 * HD; i += HD) ws[i] = w[i];
    bs[c] = b[c];
    int n0 = blockIdx.x * 16;
    for (int i = c; i < 16 * 15; i += HD) {
        int nn = i / 15, kk = i % 15;
        int g = n0 + nn;
        xs[i] = (g < NN) ? x[g * 15 + kk] : 0.0f;
    }
    __syncthreads();
    for (int r = 0; r < 16; r++) {
        int g = n0 + r;
        if (g >= NN) break;
        float acc = bs[c];
#pragma unroll
        for (int k = 0; k < 15; k++) acc += xs[r * 15 + k] * ws[k * HD + c];
        h[g * HD + c] = acc;
    }
}

__global__ void build_w2u(const float* __restrict__ msg_w2,
                          const float* __restrict__ msg_b2,
                          const float* __restrict__ upd_w1,
                          float* __restrict__ W2U,
                          float* __restrict__ cvec) {
    int l = blockIdx.y, k = blockIdx.x, c = threadIdx.x;
    const float* u1b = upd_w1 + l * 256 * HD + 128 * HD;
    if (k < HD) {
        const float* wrow = msg_w2 + (l * HD + k) * HD;
        float acc = 0.0f;
        for (int j = 0; j < HD; j++) acc += wrow[j] * u1b[j * HD + c];
        W2U[(l * HD + k) * HD + c] = acc;
    } else {
        const float* brow = msg_b2 + l * HD;
        float acc = 0.0f;
        for (int j = 0; j < HD; j++) acc += brow[j] * u1b[j * HD + c];
        cvec[l * HD + c] = acc;
    }
}

// ---------------- CSR gather aggregation -> pre-split Ysp -----------------------
__global__ void __launch_bounds__(256) aggregate_k(
    const int* __restrict__ rowptr,
    const int2* __restrict__ epack,
    const float* __restrict__ P1,
    const float* __restrict__ P2,
    const float* __restrict__ w1c,
    unsigned long long* __restrict__ Ysp) {
    int node = blockIdx.x * 8 + (threadIdx.x >> 5);
    int lane = threadIdx.x & 31;
    int c4 = lane * 4;
    const float4 cw = *(const float4*)&w1c[c4];
    const float4 p1 = *(const float4*)&P1[node * HD + c4];
    float a0 = 0.f, a1 = 0.f, a2 = 0.f, a3 = 0.f;
    float b0 = 0.f, b1 = 0.f, b2 = 0.f, b3 = 0.f;
    float c0 = 0.f, c1 = 0.f, c2 = 0.f, c3 = 0.f;
    float d0 = 0.f, d1 = 0.f, d2 = 0.f, d3 = 0.f;
    int beg = rowptr[node], end = rowptr[node + 1];
    int e = beg;
    for (; e + 3 < end; e += 4) {
        int2 q0 = epack[e], q1 = epack[e + 1], q2 = epack[e + 2], q3 = epack[e + 3];
        const float4 v0 = *(const float4*)&P2[q0.x * HD + c4];
        const float4 v1 = *(const float4*)&P2[q1.x * HD + c4];
        const float4 v2 = *(const float4*)&P2[q2.x * HD + c4];
        const float4 v3 = *(const float4*)&P2[q3.x * HD + c4];
        float dd0 = __int_as_float(q0.y), dd1 = __int_as_float(q1.y);
        float dd2 = __int_as_float(q2.y), dd3 = __int_as_float(q3.y);
        a0 += fmaxf(p1.x + v0.x + dd0 * cw.x, 0.0f);
        a1 += fmaxf(p1.y + v0.y + dd0 * cw.y, 0.0f);
        a2 += fmaxf(p1.z + v0.z + dd0 * cw.z, 0.0f);
        a3 += fmaxf(p1.w + v0.w + dd0 * cw.w, 0.0f);
        b0 += fmaxf(p1.x + v1.x + dd1 * cw.x, 0.0f);
        b1 += fmaxf(p1.y + v1.y + dd1 * cw.y, 0.0f);
        b2 += fmaxf(p1.z + v1.z + dd1 * cw.z, 0.0f);
        b3 += fmaxf(p1.w + v1.w + dd1 * cw.w, 0.0f);
        c0 += fmaxf(p1.x + v2.x + dd2 * cw.x, 0.0f);
        c1 += fmaxf(p1.y + v2.y + dd2 * cw.y, 0.0f);
        c2 += fmaxf(p1.z + v2.z + dd2 * cw.z, 0.0f);
        c3 += fmaxf(p1.w + v2.w + dd2 * cw.w, 0.0f);
        d0 += fmaxf(p1.x + v3.x + dd3 * cw.x, 0.0f);
        d1 += fmaxf(p1.y + v3.y + dd3 * cw.y, 0.0f);
        d2 += fmaxf(p1.z + v3.z + dd3 * cw.z, 0.0f);
        d3 += fmaxf(p1.w + v3.w + dd3 * cw.w, 0.0f);
    }
    for (; e < end; e++) {
        int2 q0 = epack[e];
        const float4 v0 = *(const float4*)&P2[q0.x * HD + c4];
        float dd0 = __int_as_float(q0.y);
        a0 += fmaxf(p1.x + v0.x + dd0 * cw.x, 0.0f);
        a1 += fmaxf(p1.y + v0.y + dd0 * cw.y, 0.0f);
        a2 += fmaxf(p1.z + v0.z + dd0 * cw.z, 0.0f);
        a3 += fmaxf(p1.w + v0.w + dd0 * cw.w, 0.0f);
    }
    float y0 = (a0 + b0) + (c0 + d0);
    float y1 = (a1 + b1) + (c1 + d1);
    float y2 = (a2 + b2) + (c2 + d2);
    float y3 = (a3 + b3) + (c3 + d3);
    Ysp[node * 64 + (c4 >> 1)] = sp2(y0, y1);
    Ysp[node * 64 + (c4 >> 1) + 1] = sp2(y2, y3);
}

// ---------------- readout --------------------------------------------------------
__global__ void pool_k(const float* __restrict__ h,
                       const int* __restrict__ batch,
                       float* __restrict__ pooled, float* __restrict__ cnt) {
    int nidx = blockIdx.x * 8 + (threadIdx.x >> 5);
    int lane = threadIdx.x & 31;
    if (nidx >= NN) return;
    int g = batch[nidx];
    float4 v = *(const float4*)&h[nidx * HD + lane * 4];
    float* p = &pooled[g * HD + lane * 4];
    atomicAdd(p + 0, v.x);
    atomicAdd(p + 1, v.y);
    atomicAdd(p + 2, v.z);
    atomicAdd(p + 3, v.w);
    if (lane == 0) atomicAdd(&cnt[g], 1.0f);
}

__global__ void readout_k(const float* __restrict__ pooled,
                          const float* __restrict__ cnt,
                          const float* __restrict__ w1, const float* __restrict__ b1,
                          const float* __restrict__ w2, const float* __restrict__ b2,
                          const float* __restrict__ w3, const float* __restrict__ b3,
                          float* __restrict__ out) {
    __shared__ float p[HD];
    __shared__ float o1s[HD];
    __shared__ float o2s[64];
    int g = blockIdx.x, c = threadIdx.x;
    float cc = fmaxf(cnt[g], 1.0f);
    p[c] = pooled[g * HD + c] / cc;
    __syncthreads();
    float acc = b1[c];
    for (int k = 0; k < HD; k++) acc += p[k] * w1[k * HD + c];
    o1s[c] = fmaxf(acc, 0.0f);
    __syncthreads();
    if (c < 64) {
        float a = b2[c];
        for (int k = 0; k < HD; k++) a += o1s[k] * w2[k * 64 + c];
        o2s[c] = fmaxf(a, 0.0f);
    }
    __syncthreads();
    if (c == 0) {
        float a = b3[0];
        for (int k = 0; k < 64; k++) a += o2s[k] * w3[k];
        out[g] = a;
    }
}

// ---------------- launch ----------------------------------------------------------
extern "C" void kernel_launch(void* const* d_in, const int* in_sizes, int n_in,
                              void* d_out, int out_size) {
    const float* x       = (const float*)d_in[0];
    const int*   ei      = (const int*)d_in[1];
    const float* pos     = (const float*)d_in[3];
    const int*   batch   = (const int*)d_in[4];
    const float* enc_w   = (const float*)d_in[5];
    const float* enc_b   = (const float*)d_in[6];
    const float* msg_w1  = (const float*)d_in[9];
    const float* msg_b1  = (const float*)d_in[10];
    const float* msg_w2  = (const float*)d_in[11];
    const float* msg_b2  = (const float*)d_in[12];
    const float* upd_w1  = (const float*)d_in[13];
    const float* upd_b1  = (const float*)d_in[14];
    const float* upd_w2  = (const float*)d_in[15];
    const float* upd_b2  = (const float*)d_in[16];
    const float* ln_g    = (const float*)d_in[17];
    const float* ln_b    = (const float*)d_in[18];
    const float* mlp_w1  = (const float*)d_in[19];
    const float* mlp_b1  = (const float*)d_in[20];
    const float* mlp_w2  = (const float*)d_in[21];
    const float* mlp_b2  = (const float*)d_in[22];
    const float* mlp_w3  = (const float*)d_in[23];
    const float* mlp_b3  = (const float*)d_in[24];
    float*       out     = (float*)d_out;

    float *h, *P1, *P2, *degf, *W2U, *cvec, *pooled, *cnt;
    int *rowptr, *cursor, *bsum;
    int2 *epack;
    unsigned *wi;
    unsigned long long *hsp, *Ysp, *Tsp;
    cudaGetSymbolAddress((void**)&h, d_h);
    cudaGetSymbolAddress((void**)&P1, d_P1);
    cudaGetSymbolAddress((void**)&P2, d_P2);
    cudaGetSymbolAddress((void**)&degf, d_degf);
    cudaGetSymbolAddress((void**)&W2U, d_W2U);
    cudaGetSymbolAddress((void**)&cvec, d_cvec);
    cudaGetSymbolAddress((void**)&pooled, d_pooled);
    cudaGetSymbolAddress((void**)&cnt, d_cnt);
    cudaGetSymbolAddress((void**)&rowptr, d_rowptr);
    cudaGetSymbolAddress((void**)&cursor, d_cursor);
    cudaGetSymbolAddress((void**)&bsum, d_bsum);
    cudaGetSymbolAddress((void**)&epack, d_epack);
    cudaGetSymbolAddress((void**)&wi, d_wi);
    cudaGetSymbolAddress((void**)&hsp, d_hsp);
    cudaGetSymbolAddress((void**)&Ysp, d_Ysp);
    cudaGetSymbolAddress((void**)&Tsp, d_Tsp);

    cudaFuncSetAttribute(p12_tc,  cudaFuncAttributeMaxDynamicSharedMemorySize, BTILE);
    cudaFuncSetAttribute(upd2_tc, cudaFuncAttributeMaxDynamicSharedMemorySize, BTILE);
    cudaFuncSetAttribute(upd3_tc, cudaFuncAttributeMaxDynamicSharedMemorySize, BTILE);

    // ---- prep; launch #4 = layer-0 p12 so ncu captures it ----
    encoder_k<<<(NN + 15) / 16, 128>>>(x, enc_w, enc_b, h);               // 1
    split_msg<<<dim3(128, 8), 64>>>(msg_w1, wi);                          // 2
    h2sp_k<<<(NN * 64 + 255) / 256, 256>>>(h, hsp);                       // 3
    p12_tc<<<2 * G128, 256, BTILE>>>(hsp, wi, msg_b1, P1, P2);            // 4 (profiled)
    zero_int<<<(NN + 255) / 256, 256>>>(cursor, NN);                      // 5
    count_k<<<(EE + 255) / 256, 256>>>(ei, cursor);                       // 6
    scan_part<<<NB, 256>>>(cursor, rowptr, bsum);                         // 7
    scan_bsum<<<1, 256>>>(bsum);                                          // 8
    add_off<<<NB, 256>>>(rowptr, bsum, cursor);                           // 9
    degf_k<<<(NN + 255) / 256, 256>>>(rowptr, degf);                      // 10
    scatter_k<<<(EE + 255) / 256, 256>>>(ei, pos, cursor, epack);         // 11
    build_w2u<<<dim3(129, 4), 128>>>(msg_w2, msg_b2, upd_w1, W2U, cvec);  // 12
    split_upd<<<dim3(128, 12), 64>>>(upd_w1, W2U, upd_w2, wi);            // 13
    zero_k<<<(NG * HD + 255) / 256, 256>>>(pooled, NG * HD);              // 14
    zero_k<<<1, 64>>>(cnt, NG);                                           // 15

    for (int l = 0; l < NLAY; l++) {
        const float* w1l = msg_w1 + l * 257 * HD;
        if (l > 0) {
            p12_tc<<<2 * G128, 256, BTILE>>>(hsp, wi + (2 * l) * 16384,
                                             msg_b1 + l * HD, P1, P2);
        }
        aggregate_k<<<NN / 8, 256>>>(rowptr, epack, P1, P2,
                                     w1l + 256 * HD, Ysp);
        upd2_tc<<<G128, 256, BTILE>>>(hsp, Ysp,
                                      wi + (8 + l) * 16384, wi + (12 + l) * 16384,
                                      upd_b1 + l * HD, degf, cvec + l * HD, Tsp);
        upd3_tc<<<G128, 256, BTILE>>>(Tsp, wi + (16 + l) * 16384,
                                      upd_b2 + l * HD, ln_g + l * HD, ln_b + l * HD,
                                      (l > 0) ? 1 : 0, h, hsp);
    }

    pool_k<<<(NN + 7) / 8, 256>>>(h, batch, pooled, cnt);
    readout_k<<<NG, 128>>>(pooled, cnt, mlp_w1, mlp_b1, mlp_w2, mlp_b2,
                           mlp_w3, mlp_b3, out);
}

// round 16
// speedup vs baseline: 1.1085x; 1.1085x over previous
#include <cuda_runtime.h>
#include <cuda_bf16.h>

#define NN 50000
#define EE 500000
#define HD 128
#define NLAY 4
#define NG 64
#define NB 196
#define G128 391

// interleaved split-weight matrices: 20 x [128 n][128 words]
// word[kw*2] = bf16x2 hi (k=2kw,2kw+1); word[kw*2+1] = bf16x2 lo
// idx 0..7 = msg W1a/W1b ; 8..11 = U1a[l] ; 12..15 = W2U[l] ; 16..19 = U2[l]
__device__ __align__(16) unsigned d_wi[20 * 16384];

__device__ __align__(16) float d_h[NN * HD];
__device__ __align__(16) float d_P1[NN * HD];
__device__ __align__(16) float d_P2[NN * HD];
__device__ __align__(16) float d_Yagg[NN * HD];
__device__ __align__(16) float d_T[NN * HD];
__device__ __align__(16) float d_degf[NN];
__device__ __align__(16) float d_W2U[NLAY * HD * HD];
__device__ __align__(16) float d_cvec[NLAY * HD];
__device__ __align__(16) float d_pooled[NG * HD];
__device__ __align__(16) float d_cnt[NG];
__device__ __align__(16) int   d_rowptr[NN + 1];
__device__ __align__(16) int   d_cursor[NN];
__device__ __align__(16) int   d_bsum[256];
__device__ __align__(16) int2  d_epack[EE];

// ---------------- helpers -------------------------------------------------------
__device__ __forceinline__ unsigned smem_u32(const void* p) {
    unsigned r;
    asm("{ .reg .u64 t; cvta.to.shared.u64 t, %1; cvt.u32.u64 %0, t; }"
        : "=r"(r) : "l"(p));
    return r;
}
__device__ __forceinline__ void cp16(unsigned saddr, const void* g) {
    asm volatile("cp.async.cg.shared.global [%0], [%1], 16;" :: "r"(saddr), "l"(g));
}
__device__ __forceinline__ void cp_commit_wait() {
    asm volatile("cp.async.commit_group;");
    asm volatile("cp.async.wait_group 0;");
}

__device__ __forceinline__ void mma_bf16(float c[4], const unsigned a[4],
                                         unsigned b0, unsigned b1) {
    asm volatile(
        "mma.sync.aligned.m16n8k16.row.col.f32.bf16.bf16.f32 "
        "{%0,%1,%2,%3}, {%4,%5,%6,%7}, {%8,%9}, {%0,%1,%2,%3};"
        : "+f"(c[0]), "+f"(c[1]), "+f"(c[2]), "+f"(c[3])
        : "r"(a[0]), "r"(a[1]), "r"(a[2]), "r"(a[3]), "r"(b0), "r"(b1));
}

// fast split: packed cvt + reconstruct-hi + packed cvt of residual
__device__ __forceinline__ void split2(float2 f, unsigned& hi, unsigned& lo) {
    unsigned h;
    asm("cvt.rn.bf16x2.f32 %0, %1, %2;" : "=r"(h) : "f"(f.y), "f"(f.x));
    float h0 = __uint_as_float(h << 16);
    float h1 = __uint_as_float(h & 0xFFFF0000u);
    unsigned l;
    float ry = f.y - h1, rx = f.x - h0;
    asm("cvt.rn.bf16x2.f32 %0, %1, %2;" : "=r"(l) : "f"(ry), "f"(rx));
    hi = h; lo = l;
}

// ---------------- HMMA building blocks ------------------------------------------
#define BROW 136
#define BTILE 69632

__device__ __forceinline__ void stageB(unsigned sb, const unsigned* __restrict__ wi,
                                       int tid, int nthr) {
    for (int c = tid; c < 4096; c += nthr) {
        int n = c >> 5;
        int c4 = c & 31;
        cp16(sb + (unsigned)((n * BROW + c4 * 4) * 4), wi + n * 128 + c4 * 4);
    }
}

__device__ __forceinline__ void loadA_frag(const float* __restrict__ A,
                                           int cr0, int cr1, int k0, int tig,
                                           unsigned ahi[4], unsigned alo[4]) {
    float2 f00 = *(const float2*)(A + cr0 * HD + k0 + tig * 2);
    float2 f10 = *(const float2*)(A + cr1 * HD + k0 + tig * 2);
    float2 f01 = *(const float2*)(A + cr0 * HD + k0 + tig * 2 + 8);
    float2 f11 = *(const float2*)(A + cr1 * HD + k0 + tig * 2 + 8);
    split2(f00, ahi[0], alo[0]);
    split2(f10, ahi[1], alo[1]);
    split2(f01, ahi[2], alo[2]);
    split2(f11, ahi[3], alo[3]);
}

// 16x128 warp tile variant
__device__ __forceinline__ void mma3_tiles(float acc[16][4], const char* __restrict__ smB,
                                           int k0, int g, int tig,
                                           const unsigned ahi[4], const unsigned alo[4]) {
    int kwofs = ((k0 >> 1) + tig) * 2;
#pragma unroll
    for (int t = 0; t < 16; t++) {
        int n = t * 8 + g;
        const char* base = smB + (n * BROW + kwofs) * 4;
        unsigned long long q0 = *(const unsigned long long*)(base);
        unsigned long long q1 = *(const unsigned long long*)(base + 32);
        unsigned bh0 = (unsigned)q0, bl0 = (unsigned)(q0 >> 32);
        unsigned bh1 = (unsigned)q1, bl1 = (unsigned)(q1 >> 32);
        mma_bf16(acc[t], ahi, bh0, bh1);
        mma_bf16(acc[t], ahi, bl0, bl1);
        mma_bf16(acc[t], alo, bh0, bh1);
    }
}

// 32x64 warp tile variant: 8 n-tiles, 2 row-sets sharing each B fragment
__device__ __forceinline__ void mma_step64(float acc0[8][4], float acc1[8][4],
                                           const char* __restrict__ smB,
                                           int k0, int nbase, int tig,
                                           const unsigned ahi0[4], const unsigned alo0[4],
                                           const unsigned ahi1[4], const unsigned alo1[4]) {
    int kwofs = ((k0 >> 1) + tig) * 2;
#pragma unroll
    for (int t = 0; t < 8; t++) {
        int n = nbase + t * 8;
        const char* base = smB + (n * BROW + kwofs) * 4;
        unsigned long long q0 = *(const unsigned long long*)(base);
        unsigned long long q1 = *(const unsigned long long*)(base + 32);
        unsigned bh0 = (unsigned)q0, bl0 = (unsigned)(q0 >> 32);
        unsigned bh1 = (unsigned)q1, bl1 = (unsigned)(q1 >> 32);
        mma_bf16(acc0[t], ahi0, bh0, bh1);
        mma_bf16(acc0[t], ahi0, bl0, bl1);
        mma_bf16(acc0[t], alo0, bh0, bh1);
        mma_bf16(acc1[t], ahi1, bh0, bh1);
        mma_bf16(acc1[t], ahi1, bl0, bl1);
        mma_bf16(acc1[t], alo1, bh0, bh1);
    }
}

// ---------------- p12: P1/P2 message GEMM (16x128 warp tile) --------------------
// 256 thr, 8 warps x 16 rows = 128 rows. Blocks [0,391) -> P1, [391,782) -> P2.
__global__ void __launch_bounds__(256) p12_tc(
    const float* __restrict__ A,
    const unsigned* __restrict__ wiPair,
    const float* __restrict__ bias,
    float* __restrict__ O1, float* __restrict__ O2) {
    extern __shared__ char smc[];
    unsigned sb = smem_u32(smc);
    int tid = threadIdx.x;
    int wid = tid >> 5, lane = tid & 31;
    int g = lane >> 2, tig = lane & 3;

    int pr = (blockIdx.x >= G128) ? 1 : 0;
    int blk = blockIdx.x - pr * G128;

    stageB(sb, wiPair + pr * 16384, tid, 256);
    cp_commit_wait();
    __syncthreads();

    int rowbase = blk * 128 + wid * 16;
    int r0 = rowbase + g, r1 = rowbase + g + 8;
    int cr0 = (r0 < NN) ? r0 : (NN - 1);
    int cr1 = (r1 < NN) ? r1 : (NN - 1);

    float acc[16][4];
#pragma unroll
    for (int i = 0; i < 16; i++)
#pragma unroll
        for (int j = 0; j < 4; j++) acc[i][j] = 0.0f;

#pragma unroll
    for (int ks = 0; ks < 8; ks++) {
        int k0 = ks * 16;
        unsigned ahi[4], alo[4];
        loadA_frag(A, cr0, cr1, k0, tig, ahi, alo);
        mma3_tiles(acc, smc, k0, g, tig, ahi, alo);
    }

    float* Op = pr ? O2 : O1;
#pragma unroll
    for (int t = 0; t < 16; t++) {
        int col = t * 8 + tig * 2;
        float2 bv = make_float2(0.f, 0.f);
        if (pr == 0) bv = *(const float2*)&bias[col];
        float2 v0 = make_float2(acc[t][0] + bv.x, acc[t][1] + bv.y);
        float2 v1 = make_float2(acc[t][2] + bv.x, acc[t][3] + bv.y);
        if (r0 < NN) *(float2*)(Op + r0 * HD + col) = v0;
        if (r1 < NN) *(float2*)(Op + r1 * HD + col) = v1;
    }
}

// ---------------- upd2: T = relu(h@U1a + Yagg@W2U + deg*cvec + bias) ------------
// 32x64 warp tile; sequential staging of the two matrices.
__global__ void __launch_bounds__(256, 2) upd2_tc(
    const float* __restrict__ A0, const float* __restrict__ A1,
    const unsigned* __restrict__ wi0, const unsigned* __restrict__ wi1,
    const float* __restrict__ bias, const float* __restrict__ degf,
    const float* __restrict__ cvec, float* __restrict__ Out) {
    extern __shared__ char smc[];
    unsigned sb = smem_u32(smc);
    int tid = threadIdx.x;
    int wid = tid >> 5, lane = tid & 31;
    int g = lane >> 2, tig = lane & 3;
    int rg = wid >> 1, cg = wid & 1;

    stageB(sb, wi0, tid, 256);
    cp_commit_wait();
    __syncthreads();

    int rowbase = blockIdx.x * 128 + rg * 32;
    int rA0 = rowbase + g, rA1 = rowbase + g + 8;
    int rB0 = rowbase + g + 16, rB1 = rowbase + g + 24;
    int cA0 = (rA0 < NN) ? rA0 : (NN - 1);
    int cA1 = (rA1 < NN) ? rA1 : (NN - 1);
    int cB0 = (rB0 < NN) ? rB0 : (NN - 1);
    int cB1 = (rB1 < NN) ? rB1 : (NN - 1);
    int nbase = cg * 64 + g;

    float acc0[8][4], acc1[8][4];
#pragma unroll
    for (int i = 0; i < 8; i++)
#pragma unroll
        for (int j = 0; j < 4; j++) { acc0[i][j] = 0.0f; acc1[i][j] = 0.0f; }

#pragma unroll
    for (int ks = 0; ks < 8; ks++) {
        int k0 = ks * 16;
        unsigned ahi0[4], alo0[4], ahi1[4], alo1[4];
        loadA_frag(A0, cA0, cA1, k0, tig, ahi0, alo0);
        loadA_frag(A0, cB0, cB1, k0, tig, ahi1, alo1);
        mma_step64(acc0, acc1, smc, k0, nbase, tig, ahi0, alo0, ahi1, alo1);
    }
    __syncthreads();
    stageB(sb, wi1, tid, 256);
    cp_commit_wait();
    __syncthreads();
#pragma unroll
    for (int ks = 0; ks < 8; ks++) {
        int k0 = ks * 16;
        unsigned ahi0[4], alo0[4], ahi1[4], alo1[4];
        loadA_frag(A1, cA0, cA1, k0, tig, ahi0, alo0);
        loadA_frag(A1, cB0, cB1, k0, tig, ahi1, alo1);
        mma_step64(acc0, acc1, smc, k0, nbase, tig, ahi0, alo0, ahi1, alo1);
    }

    float dgA0 = degf[cA0], dgA1 = degf[cA1];
    float dgB0 = degf[cB0], dgB1 = degf[cB1];
#pragma unroll
    for (int t = 0; t < 8; t++) {
        int col = cg * 64 + t * 8 + tig * 2;
        float2 bv = *(const float2*)&bias[col];
        float2 cv = *(const float2*)&cvec[col];
        float2 v;
        v.x = fmaxf(acc0[t][0] + dgA0 * cv.x + bv.x, 0.0f);
        v.y = fmaxf(acc0[t][1] + dgA0 * cv.y + bv.y, 0.0f);
        if (rA0 < NN) *(float2*)(Out + rA0 * HD + col) = v;
        v.x = fmaxf(acc0[t][2] + dgA1 * cv.x + bv.x, 0.0f);
        v.y = fmaxf(acc0[t][3] + dgA1 * cv.y + bv.y, 0.0f);
        if (rA1 < NN) *(float2*)(Out + rA1 * HD + col) = v;
        v.x = fmaxf(acc1[t][0] + dgB0 * cv.x + bv.x, 0.0f);
        v.y = fmaxf(acc1[t][1] + dgB0 * cv.y + bv.y, 0.0f);
        if (rB0 < NN) *(float2*)(Out + rB0 * HD + col) = v;
        v.x = fmaxf(acc1[t][2] + dgB1 * cv.x + bv.x, 0.0f);
        v.y = fmaxf(acc1[t][3] + dgB1 * cv.y + bv.y, 0.0f);
        if (rB1 < NN) *(float2*)(Out + rB1 * HD + col) = v;
    }
}

// ---------------- upd3: h = (res? h:0) + relu(LN(T@U2 + bias)) ------------------
// 16x128 warp tile (LN needs the full row inside one warp)
__global__ void __launch_bounds__(256, 2) upd3_tc(
    const float* __restrict__ A,
    const unsigned* __restrict__ wiU,
    const float* __restrict__ bias,
    const float* __restrict__ lng, const float* __restrict__ lnb,
    int addres, float* __restrict__ Out) {
    extern __shared__ char smc[];
    unsigned sb = smem_u32(smc);
    int tid = threadIdx.x;
    int wid = tid >> 5, lane = tid & 31;
    int g = lane >> 2, tig = lane & 3;

    stageB(sb, wiU, tid, 256);
    cp_commit_wait();
    __syncthreads();

    int rowbase = blockIdx.x * 128 + wid * 16;
    int r0 = rowbase + g, r1 = rowbase + g + 8;
    int cr0 = (r0 < NN) ? r0 : (NN - 1);
    int cr1 = (r1 < NN) ? r1 : (NN - 1);

    float acc[16][4];
#pragma unroll
    for (int i = 0; i < 16; i++)
#pragma unroll
        for (int j = 0; j < 4; j++) acc[i][j] = 0.0f;

#pragma unroll
    for (int ks = 0; ks < 8; ks++) {
        int k0 = ks * 16;
        unsigned ahi[4], alo[4];
        loadA_frag(A, cr0, cr1, k0, tig, ahi, alo);
        mma3_tiles(acc, smc, k0, g, tig, ahi, alo);
    }

    float s0 = 0.f, sq0 = 0.f, s1 = 0.f, sq1 = 0.f;
#pragma unroll
    for (int t = 0; t < 16; t++) {
        int col = t * 8 + tig * 2;
        float2 bv = *(const float2*)&bias[col];
        acc[t][0] += bv.x; acc[t][1] += bv.y;
        acc[t][2] += bv.x; acc[t][3] += bv.y;
        s0 += acc[t][0] + acc[t][1];
        sq0 += acc[t][0] * acc[t][0] + acc[t][1] * acc[t][1];
        s1 += acc[t][2] + acc[t][3];
        sq1 += acc[t][2] * acc[t][2] + acc[t][3] * acc[t][3];
    }
#pragma unroll
    for (int off = 1; off <= 2; off <<= 1) {
        s0 += __shfl_xor_sync(0xffffffffu, s0, off);
        sq0 += __shfl_xor_sync(0xffffffffu, sq0, off);
        s1 += __shfl_xor_sync(0xffffffffu, s1, off);
        sq1 += __shfl_xor_sync(0xffffffffu, sq1, off);
    }
    float mu0 = s0 * (1.0f / HD);
    float mu1 = s1 * (1.0f / HD);
    float rstd0 = rsqrtf(sq0 * (1.0f / HD) - mu0 * mu0 + 1e-5f);
    float rstd1 = rsqrtf(sq1 * (1.0f / HD) - mu1 * mu1 + 1e-5f);

#pragma unroll
    for (int t = 0; t < 16; t++) {
        int col = t * 8 + tig * 2;
        float2 gv = *(const float2*)&lng[col];
        float2 lv = *(const float2*)&lnb[col];
        float2 v0, v1;
        v0.x = fmaxf((acc[t][0] - mu0) * rstd0 * gv.x + lv.x, 0.0f);
        v0.y = fmaxf((acc[t][1] - mu0) * rstd0 * gv.y + lv.y, 0.0f);
        v1.x = fmaxf((acc[t][2] - mu1) * rstd1 * gv.x + lv.x, 0.0f);
        v1.y = fmaxf((acc[t][3] - mu1) * rstd1 * gv.y + lv.y, 0.0f);
        if (r0 < NN) {
            if (addres) {
                float2 hv = *(const float2*)(Out + r0 * HD + col);
                v0.x += hv.x; v0.y += hv.y;
            }
            *(float2*)(Out + r0 * HD + col) = v0;
        }
        if (r1 < NN) {
            if (addres) {
                float2 hv = *(const float2*)(Out + r1 * HD + col);
                v1.x += hv.x; v1.y += hv.y;
            }
            *(float2*)(Out + r1 * HD + col) = v1;
        }
    }
}

// ---------------- weight transpose + split + interleave -------------------------
__device__ __forceinline__ void split_store(unsigned* __restrict__ dst,
                                            int m, int n, int kw,
                                            float v0, float v1) {
    __nv_bfloat16 h0 = __float2bfloat16(v0), h1 = __float2bfloat16(v1);
    __nv_bfloat16 l0 = __float2bfloat16(v0 - __bfloat162float(h0));
    __nv_bfloat16 l1 = __float2bfloat16(v1 - __bfloat162float(h1));
    dst[m * 16384 + n * 128 + kw * 2] =
        ((unsigned)__bfloat16_as_ushort(h1) << 16) | __bfloat16_as_ushort(h0);
    dst[m * 16384 + n * 128 + kw * 2 + 1] =
        ((unsigned)__bfloat16_as_ushort(l1) << 16) | __bfloat16_as_ushort(l0);
}

__global__ void split_msg(const float* __restrict__ msg_w1, unsigned* __restrict__ wi) {
    int n = blockIdx.x, m = blockIdx.y, kw = threadIdx.x;
    int l = m >> 1, part = m & 1;
    const float* W = msg_w1 + l * 257 * HD + part * 128 * HD;
    split_store(wi, m, n, kw, W[(2 * kw) * HD + n], W[(2 * kw + 1) * HD + n]);
}

__global__ void split_upd(const float* __restrict__ upd_w1,
                          const float* __restrict__ W2U,
                          const float* __restrict__ upd_w2,
                          unsigned* __restrict__ wi) {
    int n = blockIdx.x, m2 = blockIdx.y, kw = threadIdx.x;
    const float* W;
    if (m2 < 4)       W = upd_w1 + m2 * 256 * HD;
    else if (m2 < 8)  W = W2U + (m2 - 4) * HD * HD;
    else              W = upd_w2 + (m2 - 8) * HD * HD;
    split_store(wi, 8 + m2, n, kw, W[(2 * kw) * HD + n], W[(2 * kw + 1) * HD + n]);
}

// ---------------- tiny utility kernels ------------------------------------------
__global__ void zero_k(float* __restrict__ p, int n) {
    int i = blockIdx.x * blockDim.x + threadIdx.x;
    if (i < n) p[i] = 0.0f;
}
__global__ void zero_int(int* __restrict__ p, int n) {
    int i = blockIdx.x * blockDim.x + threadIdx.x;
    if (i < n) p[i] = 0;
}

// ---------------- CSR build ------------------------------------------------------
__global__ void count_k(const int* __restrict__ ei, int* __restrict__ deg) {
    int e = blockIdx.x * blockDim.x + threadIdx.x;
    if (e < EE) atomicAdd(&deg[ei[EE + e]], 1);
}

__global__ void scan_part(const int* __restrict__ deg, int* __restrict__ rowptr,
                          int* __restrict__ bsum) {
    __shared__ int s[256];
    int tid = threadIdx.x;
    int i = blockIdx.x * 256 + tid;
    int v = (i < NN) ? deg[i] : 0;
    s[tid] = v;
    __syncthreads();
#pragma unroll
    for (int off = 1; off < 256; off <<= 1) {
        int t = (tid >= off) ? s[tid - off] : 0;
        __syncthreads();
        s[tid] += t;
        __syncthreads();
    }
    if (i < NN) rowptr[i] = s[tid] - v;
    if (tid == 255) bsum[blockIdx.x] = s[255];
}

__global__ void scan_bsum(int* __restrict__ bsum) {
    __shared__ int s[256];
    int tid = threadIdx.x;
    int v = (tid < NB) ? bsum[tid] : 0;
    s[tid] = v;
    __syncthreads();
#pragma unroll
    for (int off = 1; off < 256; off <<= 1) {
        int t = (tid >= off) ? s[tid - off] : 0;
        __syncthreads();
        s[tid] += t;
        __syncthreads();
    }
    if (tid < NB) bsum[tid] = s[tid] - v;
}

__global__ void add_off(int* __restrict__ rowptr, const int* __restrict__ bsum,
                        int* __restrict__ cursor) {
    int i = blockIdx.x * 256 + threadIdx.x;
    if (i < NN) {
        int r = rowptr[i] + bsum[blockIdx.x];
        rowptr[i] = r;
        cursor[i] = r;
    }
    if (i == 0) rowptr[NN] = EE;
}

__global__ void degf_k(const int* __restrict__ rowptr, float* __restrict__ degf) {
    int i = blockIdx.x * blockDim.x + threadIdx.x;
    if (i < NN) degf[i] = (float)(rowptr[i + 1] - rowptr[i]);
}

__global__ void scatter_k(const int* __restrict__ ei,
                          const float* __restrict__ pos,
                          int* __restrict__ cursor,
                          int2* __restrict__ epack) {
    int e = blockIdx.x * blockDim.x + threadIdx.x;
    if (e >= EE) return;
    int s = ei[e];
    int t = ei[EE + e];
    float dx = pos[t * 3 + 0] - pos[s * 3 + 0];
    float dy = pos[t * 3 + 1] - pos[s * 3 + 1];
    float dz = pos[t * 3 + 2] - pos[s * 3 + 2];
    float dd = sqrtf(dx * dx + dy * dy + dz * dz);
    int p = atomicAdd(&cursor[t], 1);
    epack[p] = make_int2(s, __float_as_int(dd));
}

// ---------------- encoder --------------------------------------------------------
__global__ void encoder_k(const float* __restrict__ x,
                          const float* __restrict__ w,
                          const float* __restrict__ b,
                          float* __restrict__ h) {
    __shared__ float ws[15 * HD];
    __shared__ float xs[16 * 15];
    __shared__ float bs[HD];
    int c = threadIdx.x;
    for (int i = c; i < 15 * HD; i += HD) ws[i] = w[i];
    bs[c] = b[c];
    int n0 = blockIdx.x * 16;
    for (int i = c; i < 16 * 15; i += HD) {
        int nn = i / 15, kk = i % 15;
        int g = n0 + nn;
        xs[i] = (g < NN) ? x[g * 15 + kk] : 0.0f;
    }
    __syncthreads();
    for (int r = 0; r < 16; r++) {
        int g = n0 + r;
        if (g >= NN) break;
        float acc = bs[c];
#pragma unroll
        for (int k = 0; k < 15; k++) acc += xs[r * 15 + k] * ws[k * HD + c];
        h[g * HD + c] = acc;
    }
}

__global__ void build_w2u(const float* __restrict__ msg_w2,
                          const float* __restrict__ msg_b2,
                          const float* __restrict__ upd_w1,
                          float* __restrict__ W2U,
                          float* __restrict__ cvec) {
    int l = blockIdx.y, k = blockIdx.x, c = threadIdx.x;
    const float* u1b = upd_w1 + l * 256 * HD + 128 * HD;
    if (k < HD) {
        const float* wrow = msg_w2 + (l * HD + k) * HD;
        float acc = 0.0f;
        for (int j = 0; j < HD; j++) acc += wrow[j] * u1b[j * HD + c];
        W2U[(l * HD + k) * HD + c] = acc;
    } else {
        const float* brow = msg_b2 + l * HD;
        float acc = 0.0f;
        for (int j = 0; j < HD; j++) acc += brow[j] * u1b[j * HD + c];
        cvec[l * HD + c] = acc;
    }
}

// ---------------- CSR gather aggregation ----------------------------------------
__global__ void __launch_bounds__(256) aggregate_k(
    const int* __restrict__ rowptr,
    const int2* __restrict__ epack,
    const float* __restrict__ P1,
    const float* __restrict__ P2,
    const float* __restrict__ w1c,
    float* __restrict__ Yagg) {
    int node = blockIdx.x * 8 + (threadIdx.x >> 5);
    int lane = threadIdx.x & 31;
    int c4 = lane * 4;
    const float4 cw = *(const float4*)&w1c[c4];
    const float4 p1 = *(const float4*)&P1[node * HD + c4];
    float a0 = 0.f, a1 = 0.f, a2 = 0.f, a3 = 0.f;
    float b0 = 0.f, b1 = 0.f, b2 = 0.f, b3 = 0.f;
    float c0 = 0.f, c1 = 0.f, c2 = 0.f, c3 = 0.f;
    float d0 = 0.f, d1 = 0.f, d2 = 0.f, d3 = 0.f;
    int beg = rowptr[node], end = rowptr[node + 1];
    int e = beg;
    for (; e + 3 < end; e += 4) {
        int2 q0 = epack[e], q1 = epack[e + 1], q2 = epack[e + 2], q3 = epack[e + 3];
        const float4 v0 = *(const float4*)&P2[q0.x * HD + c4];
        const float4 v1 = *(const float4*)&P2[q1.x * HD + c4];
        const float4 v2 = *(const float4*)&P2[q2.x * HD + c4];
        const float4 v3 = *(const float4*)&P2[q3.x * HD + c4];
        float dd0 = __int_as_float(q0.y), dd1 = __int_as_float(q1.y);
        float dd2 = __int_as_float(q2.y), dd3 = __int_as_float(q3.y);
        a0 += fmaxf(p1.x + v0.x + dd0 * cw.x, 0.0f);
        a1 += fmaxf(p1.y + v0.y + dd0 * cw.y, 0.0f);
        a2 += fmaxf(p1.z + v0.z + dd0 * cw.z, 0.0f);
        a3 += fmaxf(p1.w + v0.w + dd0 * cw.w, 0.0f);
        b0 += fmaxf(p1.x + v1.x + dd1 * cw.x, 0.0f);
        b1 += fmaxf(p1.y + v1.y + dd1 * cw.y, 0.0f);
        b2 += fmaxf(p1.z + v1.z + dd1 * cw.z, 0.0f);
        b3 += fmaxf(p1.w + v1.w + dd1 * cw.w, 0.0f);
        c0 += fmaxf(p1.x + v2.x + dd2 * cw.x, 0.0f);
        c1 += fmaxf(p1.y + v2.y + dd2 * cw.y, 0.0f);
        c2 += fmaxf(p1.z + v2.z + dd2 * cw.z, 0.0f);
        c3 += fmaxf(p1.w + v2.w + dd2 * cw.w, 0.0f);
        d0 += fmaxf(p1.x + v3.x + dd3 * cw.x, 0.0f);
        d1 += fmaxf(p1.y + v3.y + dd3 * cw.y, 0.0f);
        d2 += fmaxf(p1.z + v3.z + dd3 * cw.z, 0.0f);
        d3 += fmaxf(p1.w + v3.w + dd3 * cw.w, 0.0f);
    }
    for (; e < end; e++) {
        int2 q0 = epack[e];
        const float4 v0 = *(const float4*)&P2[q0.x * HD + c4];
        float dd0 = __int_as_float(q0.y);
        a0 += fmaxf(p1.x + v0.x + dd0 * cw.x, 0.0f);
        a1 += fmaxf(p1.y + v0.y + dd0 * cw.y, 0.0f);
        a2 += fmaxf(p1.z + v0.z + dd0 * cw.z, 0.0f);
        a3 += fmaxf(p1.w + v0.w + dd0 * cw.w, 0.0f);
    }
    *(float4*)&Yagg[node * HD + c4] = make_float4(
        (a0 + b0) + (c0 + d0), (a1 + b1) + (c1 + d1),
        (a2 + b2) + (c2 + d2), (a3 + b3) + (c3 + d3));
}

// ---------------- readout --------------------------------------------------------
__global__ void pool_k(const float* __restrict__ h,
                       const int* __restrict__ batch,
                       float* __restrict__ pooled, float* __restrict__ cnt) {
    int nidx = blockIdx.x * 8 + (threadIdx.x >> 5);
    int lane = threadIdx.x & 31;
    if (nidx >= NN) return;
    int g = batch[nidx];
    float4 v = *(const float4*)&h[nidx * HD + lane * 4];
    float* p = &pooled[g * HD + lane * 4];
    atomicAdd(p + 0, v.x);
    atomicAdd(p + 1, v.y);
    atomicAdd(p + 2, v.z);
    atomicAdd(p + 3, v.w);
    if (lane == 0) atomicAdd(&cnt[g], 1.0f);
}

__global__ void readout_k(const float* __restrict__ pooled,
                          const float* __restrict__ cnt,
                          const float* __restrict__ w1, const float* __restrict__ b1,
                          const float* __restrict__ w2, const float* __restrict__ b2,
                          const float* __restrict__ w3, const float* __restrict__ b3,
                          float* __restrict__ out) {
    __shared__ float p[HD];
    __shared__ float o1s[HD];
    __shared__ float o2s[64];
    int g = blockIdx.x, c = threadIdx.x;
    float cc = fmaxf(cnt[g], 1.0f);
    p[c] = pooled[g * HD + c] / cc;
    __syncthreads();
    float acc = b1[c];
    for (int k = 0; k < HD; k++) acc += p[k] * w1[k * HD + c];
    o1s[c] = fmaxf(acc, 0.0f);
    __syncthreads();
    if (c < 64) {
        float a = b2[c];
        for (int k = 0; k < HD; k++) a += o1s[k] * w2[k * 64 + c];
        o2s[c] = fmaxf(a, 0.0f);
    }
    __syncthreads();
    if (c == 0) {
        float a = b3[0];
        for (int k = 0; k < 64; k++) a += o2s[k] * w3[k];
        out[g] = a;
    }
}

// ---------------- launch ----------------------------------------------------------
extern "C" void kernel_launch(void* const* d_in, const int* in_sizes, int n_in,
                              void* d_out, int out_size) {
    const float* x       = (const float*)d_in[0];
    const int*   ei      = (const int*)d_in[1];
    const float* pos     = (const float*)d_in[3];
    const int*   batch   = (const int*)d_in[4];
    const float* enc_w   = (const float*)d_in[5];
    const float* enc_b   = (const float*)d_in[6];
    const float* msg_w1  = (const float*)d_in[9];
    const float* msg_b1  = (const float*)d_in[10];
    const float* msg_w2  = (const float*)d_in[11];
    const float* msg_b2  = (const float*)d_in[12];
    const float* upd_w1  = (const float*)d_in[13];
    const float* upd_b1  = (const float*)d_in[14];
    const float* upd_w2  = (const float*)d_in[15];
    const float* upd_b2  = (const float*)d_in[16];
    const float* ln_g    = (const float*)d_in[17];
    const float* ln_b    = (const float*)d_in[18];
    const float* mlp_w1  = (const float*)d_in[19];
    const float* mlp_b1  = (const float*)d_in[20];
    const float* mlp_w2  = (const float*)d_in[21];
    const float* mlp_b2  = (const float*)d_in[22];
    const float* mlp_w3  = (const float*)d_in[23];
    const float* mlp_b3  = (const float*)d_in[24];
    float*       out     = (float*)d_out;

    float *h, *P1, *P2, *Yagg, *T, *degf, *W2U, *cvec, *pooled, *cnt;
    int *rowptr, *cursor, *bsum;
    int2 *epack;
    unsigned *wi;
    cudaGetSymbolAddress((void**)&h, d_h);
    cudaGetSymbolAddress((void**)&P1, d_P1);
    cudaGetSymbolAddress((void**)&P2, d_P2);
    cudaGetSymbolAddress((void**)&Yagg, d_Yagg);
    cudaGetSymbolAddress((void**)&T, d_T);
    cudaGetSymbolAddress((void**)&degf, d_degf);
    cudaGetSymbolAddress((void**)&W2U, d_W2U);
    cudaGetSymbolAddress((void**)&cvec, d_cvec);
    cudaGetSymbolAddress((void**)&pooled, d_pooled);
    cudaGetSymbolAddress((void**)&cnt, d_cnt);
    cudaGetSymbolAddress((void**)&rowptr, d_rowptr);
    cudaGetSymbolAddress((void**)&cursor, d_cursor);
    cudaGetSymbolAddress((void**)&bsum, d_bsum);
    cudaGetSymbolAddress((void**)&epack, d_epack);
    cudaGetSymbolAddress((void**)&wi, d_wi);

    cudaFuncSetAttribute(p12_tc,  cudaFuncAttributeMaxDynamicSharedMemorySize, BTILE);
    cudaFuncSetAttribute(upd2_tc, cudaFuncAttributeMaxDynamicSharedMemorySize, BTILE);
    cudaFuncSetAttribute(upd3_tc, cudaFuncAttributeMaxDynamicSharedMemorySize, BTILE);

    // ---- prep; launch #4 = layer-0 p12 so ncu captures it ----
    encoder_k<<<(NN + 15) / 16, 128>>>(x, enc_w, enc_b, h);               // 1
    split_msg<<<dim3(128, 8), 64>>>(msg_w1, wi);                          // 2
    zero_int<<<(NN + 255) / 256, 256>>>(cursor, NN);                      // 3
    p12_tc<<<2 * G128, 256, BTILE>>>(h, wi, msg_b1, P1, P2);              // 4 (profiled)
    count_k<<<(EE + 255) / 256, 256>>>(ei, cursor);                       // 5
    scan_part<<<NB, 256>>>(cursor, rowptr, bsum);                         // 6
    scan_bsum<<<1, 256>>>(bsum);                                          // 7
    add_off<<<NB, 256>>>(rowptr, bsum, cursor);                           // 8
    degf_k<<<(NN + 255) / 256, 256>>>(rowptr, degf);                      // 9
    scatter_k<<<(EE + 255) / 256, 256>>>(ei, pos, cursor, epack);         // 10
    build_w2u<<<dim3(129, 4), 128>>>(msg_w2, msg_b2, upd_w1, W2U, cvec);  // 11
    split_upd<<<dim3(128, 12), 64>>>(upd_w1, W2U, upd_w2, wi);            // 12
    zero_k<<<(NG * HD + 255) / 256, 256>>>(pooled, NG * HD);              // 13
    zero_k<<<1, 64>>>(cnt, NG);                                           // 14

    for (int l = 0; l < NLAY; l++) {
        const float* w1l = msg_w1 + l * 257 * HD;
        if (l > 0) {
            p12_tc<<<2 * G128, 256, BTILE>>>(h, wi + (2 * l) * 16384,
                                             msg_b1 + l * HD, P1, P2);
        }
        aggregate_k<<<NN / 8, 256>>>(rowptr, epack, P1, P2,
                                     w1l + 256 * HD, Yagg);
        upd2_tc<<<G128, 256, BTILE>>>(h, Yagg,
                                      wi + (8 + l) * 16384, wi + (12 + l) * 16384,
                                      upd_b1 + l * HD, degf, cvec + l * HD, T);
        upd3_tc<<<G128, 256, BTILE>>>(T, wi + (16 + l) * 16384,
                                      upd_b2 + l * HD, ln_g + l * HD, ln_b + l * HD,
                                      (l > 0) ? 1 : 0, h);
    }

    pool_k<<<(NN + 7) / 8, 256>>>(h, batch, pooled, cnt);
    readout_k<<<NG, 128>>>(pooled, cnt, mlp_w1, mlp_b1, mlp_w2, mlp_b2,
                           mlp_w3, mlp_b3, out);
}

// round 17
// speedup vs baseline: 1.1365x; 1.0252x over previous
#include <cuda_runtime.h>
#include <cuda_bf16.h>

#define NN 50000
#define EE 500000
#define HD 128
#define NLAY 4
#define NG 64
#define NB 196
#define G128 391

// interleaved split-weight matrices: 20 x [128 n][128 words]
// word[kw*2] = bf16x2 hi (k=2kw,2kw+1); word[kw*2+1] = bf16x2 lo
// idx 0..7 = msg W1a/W1b ; 8..11 = U1a[l] ; 12..15 = W2U[l] ; 16..19 = U2[l]
__device__ __align__(16) unsigned d_wi[20 * 16384];

__device__ __align__(16) float d_h[NN * HD];
__device__ __align__(16) float d_P1[NN * HD];
__device__ __align__(16) unsigned d_P2b[NN * 64];   // P2 packed bf16x2
__device__ __align__(16) float d_Yagg[NN * HD];
__device__ __align__(16) float d_T[NN * HD];
__device__ __align__(16) float d_degf[NN];
__device__ __align__(16) float d_W2U[NLAY * HD * HD];
__device__ __align__(16) float d_cvec[NLAY * HD];
__device__ __align__(16) float d_pooled[NG * HD];
__device__ __align__(16) float d_cnt[NG];
__device__ __align__(16) int   d_rowptr[NN + 1];
__device__ __align__(16) int   d_cursor[NN];
__device__ __align__(16) int   d_bsum[256];
__device__ __align__(16) int2  d_epack[EE];

// ---------------- helpers -------------------------------------------------------
__device__ __forceinline__ unsigned smem_u32(const void* p) {
    unsigned r;
    asm("{ .reg .u64 t; cvta.to.shared.u64 t, %1; cvt.u32.u64 %0, t; }"
        : "=r"(r) : "l"(p));
    return r;
}
__device__ __forceinline__ void cp16(unsigned saddr, const void* g) {
    asm volatile("cp.async.cg.shared.global [%0], [%1], 16;" :: "r"(saddr), "l"(g));
}
__device__ __forceinline__ void cp_commit_wait() {
    asm volatile("cp.async.commit_group;");
    asm volatile("cp.async.wait_group 0;");
}

__device__ __forceinline__ void mma_bf16(float c[4], const unsigned a[4],
                                         unsigned b0, unsigned b1) {
    asm volatile(
        "mma.sync.aligned.m16n8k16.row.col.f32.bf16.bf16.f32 "
        "{%0,%1,%2,%3}, {%4,%5,%6,%7}, {%8,%9}, {%0,%1,%2,%3};"
        : "+f"(c[0]), "+f"(c[1]), "+f"(c[2]), "+f"(c[3])
        : "r"(a[0]), "r"(a[1]), "r"(a[2]), "r"(a[3]), "r"(b0), "r"(b1));
}

// fast split: packed cvt + reconstruct-hi + packed cvt of residual
__device__ __forceinline__ void split2(float2 f, unsigned& hi, unsigned& lo) {
    unsigned h;
    asm("cvt.rn.bf16x2.f32 %0, %1, %2;" : "=r"(h) : "f"(f.y), "f"(f.x));
    float h0 = __uint_as_float(h << 16);
    float h1 = __uint_as_float(h & 0xFFFF0000u);
    unsigned l;
    float ry = f.y - h1, rx = f.x - h0;
    asm("cvt.rn.bf16x2.f32 %0, %1, %2;" : "=r"(l) : "f"(ry), "f"(rx));
    hi = h; lo = l;
}
// pack (x -> low, y -> high) bf16x2
__device__ __forceinline__ unsigned pkbf2(float x, float y) {
    unsigned h;
    asm("cvt.rn.bf16x2.f32 %0, %1, %2;" : "=r"(h) : "f"(y), "f"(x));
    return h;
}

// ---------------- HMMA building blocks ------------------------------------------
#define BROW 136
#define BTILE 69632

__device__ __forceinline__ void stageB(unsigned sb, const unsigned* __restrict__ wi,
                                       int tid, int nthr) {
    for (int c = tid; c < 4096; c += nthr) {
        int n = c >> 5;
        int c4 = c & 31;
        cp16(sb + (unsigned)((n * BROW + c4 * 4) * 4), wi + n * 128 + c4 * 4);
    }
}

__device__ __forceinline__ void loadA_frag(const float* __restrict__ A,
                                           int cr0, int cr1, int k0, int tig,
                                           unsigned ahi[4], unsigned alo[4]) {
    float2 f00 = *(const float2*)(A + cr0 * HD + k0 + tig * 2);
    float2 f10 = *(const float2*)(A + cr1 * HD + k0 + tig * 2);
    float2 f01 = *(const float2*)(A + cr0 * HD + k0 + tig * 2 + 8);
    float2 f11 = *(const float2*)(A + cr1 * HD + k0 + tig * 2 + 8);
    split2(f00, ahi[0], alo[0]);
    split2(f10, ahi[1], alo[1]);
    split2(f01, ahi[2], alo[2]);
    split2(f11, ahi[3], alo[3]);
}

// 16x128 warp tile variant
__device__ __forceinline__ void mma3_tiles(float acc[16][4], const char* __restrict__ smB,
                                           int k0, int g, int tig,
                                           const unsigned ahi[4], const unsigned alo[4]) {
    int kwofs = ((k0 >> 1) + tig) * 2;
#pragma unroll
    for (int t = 0; t < 16; t++) {
        int n = t * 8 + g;
        const char* base = smB + (n * BROW + kwofs) * 4;
        unsigned long long q0 = *(const unsigned long long*)(base);
        unsigned long long q1 = *(const unsigned long long*)(base + 32);
        unsigned bh0 = (unsigned)q0, bl0 = (unsigned)(q0 >> 32);
        unsigned bh1 = (unsigned)q1, bl1 = (unsigned)(q1 >> 32);
        mma_bf16(acc[t], ahi, bh0, bh1);
        mma_bf16(acc[t], ahi, bl0, bl1);
        mma_bf16(acc[t], alo, bh0, bh1);
    }
}

// 32x64 warp tile variant: 8 n-tiles, 2 row-sets sharing each B fragment
__device__ __forceinline__ void mma_step64(float acc0[8][4], float acc1[8][4],
                                           const char* __restrict__ smB,
                                           int k0, int nbase, int tig,
                                           const unsigned ahi0[4], const unsigned alo0[4],
                                           const unsigned ahi1[4], const unsigned alo1[4]) {
    int kwofs = ((k0 >> 1) + tig) * 2;
#pragma unroll
    for (int t = 0; t < 8; t++) {
        int n = nbase + t * 8;
        const char* base = smB + (n * BROW + kwofs) * 4;
        unsigned long long q0 = *(const unsigned long long*)(base);
        unsigned long long q1 = *(const unsigned long long*)(base + 32);
        unsigned bh0 = (unsigned)q0, bl0 = (unsigned)(q0 >> 32);
        unsigned bh1 = (unsigned)q1, bl1 = (unsigned)(q1 >> 32);
        mma_bf16(acc0[t], ahi0, bh0, bh1);
        mma_bf16(acc0[t], ahi0, bl0, bl1);
        mma_bf16(acc0[t], alo0, bh0, bh1);
        mma_bf16(acc1[t], ahi1, bh0, bh1);
        mma_bf16(acc1[t], ahi1, bl0, bl1);
        mma_bf16(acc1[t], alo1, bh0, bh1);
    }
}

// ---------------- p12: P1/P2 message GEMM (16x128 warp tile) --------------------
// 256 thr, 8 warps x 16 rows = 128 rows. Blocks [0,391) -> P1 (f32), [391,782) -> P2 (bf16x2).
__global__ void __launch_bounds__(256) p12_tc(
    const float* __restrict__ A,
    const unsigned* __restrict__ wiPair,
    const float* __restrict__ bias,
    float* __restrict__ O1, unsigned* __restrict__ O2b) {
    extern __shared__ char smc[];
    unsigned sb = smem_u32(smc);
    int tid = threadIdx.x;
    int wid = tid >> 5, lane = tid & 31;
    int g = lane >> 2, tig = lane & 3;

    int pr = (blockIdx.x >= G128) ? 1 : 0;
    int blk = blockIdx.x - pr * G128;

    stageB(sb, wiPair + pr * 16384, tid, 256);
    cp_commit_wait();
    __syncthreads();

    int rowbase = blk * 128 + wid * 16;
    int r0 = rowbase + g, r1 = rowbase + g + 8;
    int cr0 = (r0 < NN) ? r0 : (NN - 1);
    int cr1 = (r1 < NN) ? r1 : (NN - 1);

    float acc[16][4];
#pragma unroll
    for (int i = 0; i < 16; i++)
#pragma unroll
        for (int j = 0; j < 4; j++) acc[i][j] = 0.0f;

#pragma unroll
    for (int ks = 0; ks < 8; ks++) {
        int k0 = ks * 16;
        unsigned ahi[4], alo[4];
        loadA_frag(A, cr0, cr1, k0, tig, ahi, alo);
        mma3_tiles(acc, smc, k0, g, tig, ahi, alo);
    }

    if (pr == 0) {
#pragma unroll
        for (int t = 0; t < 16; t++) {
            int col = t * 8 + tig * 2;
            float2 bv = *(const float2*)&bias[col];
            float2 v0 = make_float2(acc[t][0] + bv.x, acc[t][1] + bv.y);
            float2 v1 = make_float2(acc[t][2] + bv.x, acc[t][3] + bv.y);
            if (r0 < NN) *(float2*)(O1 + r0 * HD + col) = v0;
            if (r1 < NN) *(float2*)(O1 + r1 * HD + col) = v1;
        }
    } else {
#pragma unroll
        for (int t = 0; t < 16; t++) {
            int colw = (t * 8 + tig * 2) >> 1;
            if (r0 < NN) O2b[r0 * 64 + colw] = pkbf2(acc[t][0], acc[t][1]);
            if (r1 < NN) O2b[r1 * 64 + colw] = pkbf2(acc[t][2], acc[t][3]);
        }
    }
}

// ---------------- upd2: T = relu(h@U1a + Yagg@W2U + deg*cvec + bias) ------------
// 32x64 warp tile; sequential staging of the two matrices.
__global__ void __launch_bounds__(256, 2) upd2_tc(
    const float* __restrict__ A0, const float* __restrict__ A1,
    const unsigned* __restrict__ wi0, const unsigned* __restrict__ wi1,
    const float* __restrict__ bias, const float* __restrict__ degf,
    const float* __restrict__ cvec, float* __restrict__ Out) {
    extern __shared__ char smc[];
    unsigned sb = smem_u32(smc);
    int tid = threadIdx.x;
    int wid = tid >> 5, lane = tid & 31;
    int g = lane >> 2, tig = lane & 3;
    int rg = wid >> 1, cg = wid & 1;

    stageB(sb, wi0, tid, 256);
    cp_commit_wait();
    __syncthreads();

    int rowbase = blockIdx.x * 128 + rg * 32;
    int rA0 = rowbase + g, rA1 = rowbase + g + 8;
    int rB0 = rowbase + g + 16, rB1 = rowbase + g + 24;
    int cA0 = (rA0 < NN) ? rA0 : (NN - 1);
    int cA1 = (rA1 < NN) ? rA1 : (NN - 1);
    int cB0 = (rB0 < NN) ? rB0 : (NN - 1);
    int cB1 = (rB1 < NN) ? rB1 : (NN - 1);
    int nbase = cg * 64 + g;

    float acc0[8][4], acc1[8][4];
#pragma unroll
    for (int i = 0; i < 8; i++)
#pragma unroll
        for (int j = 0; j < 4; j++) { acc0[i][j] = 0.0f; acc1[i][j] = 0.0f; }

#pragma unroll
    for (int ks = 0; ks < 8; ks++) {
        int k0 = ks * 16;
        unsigned ahi0[4], alo0[4], ahi1[4], alo1[4];
        loadA_frag(A0, cA0, cA1, k0, tig, ahi0, alo0);
        loadA_frag(A0, cB0, cB1, k0, tig, ahi1, alo1);
        mma_step64(acc0, acc1, smc, k0, nbase, tig, ahi0, alo0, ahi1, alo1);
    }
    __syncthreads();
    stageB(sb, wi1, tid, 256);
    cp_commit_wait();
    __syncthreads();
#pragma unroll
    for (int ks = 0; ks < 8; ks++) {
        int k0 = ks * 16;
        unsigned ahi0[4], alo0[4], ahi1[4], alo1[4];
        loadA_frag(A1, cA0, cA1, k0, tig, ahi0, alo0);
        loadA_frag(A1, cB0, cB1, k0, tig, ahi1, alo1);
        mma_step64(acc0, acc1, smc, k0, nbase, tig, ahi0, alo0, ahi1, alo1);
    }

    float dgA0 = degf[cA0], dgA1 = degf[cA1];
    float dgB0 = degf[cB0], dgB1 = degf[cB1];
#pragma unroll
    for (int t = 0; t < 8; t++) {
        int col = cg * 64 + t * 8 + tig * 2;
        float2 bv = *(const float2*)&bias[col];
        float2 cv = *(const float2*)&cvec[col];
        float2 v;
        v.x = fmaxf(acc0[t][0] + dgA0 * cv.x + bv.x, 0.0f);
        v.y = fmaxf(acc0[t][1] + dgA0 * cv.y + bv.y, 0.0f);
        if (rA0 < NN) *(float2*)(Out + rA0 * HD + col) = v;
        v.x = fmaxf(acc0[t][2] + dgA1 * cv.x + bv.x, 0.0f);
        v.y = fmaxf(acc0[t][3] + dgA1 * cv.y + bv.y, 0.0f);
        if (rA1 < NN) *(float2*)(Out + rA1 * HD + col) = v;
        v.x = fmaxf(acc1[t][0] + dgB0 * cv.x + bv.x, 0.0f);
        v.y = fmaxf(acc1[t][1] + dgB0 * cv.y + bv.y, 0.0f);
        if (rB0 < NN) *(float2*)(Out + rB0 * HD + col) = v;
        v.x = fmaxf(acc1[t][2] + dgB1 * cv.x + bv.x, 0.0f);
        v.y = fmaxf(acc1[t][3] + dgB1 * cv.y + bv.y, 0.0f);
        if (rB1 < NN) *(float2*)(Out + rB1 * HD + col) = v;
    }
}

// ---------------- upd3: h = (res? h:0) + relu(LN(T@U2 + bias)) ------------------
__global__ void __launch_bounds__(256, 2) upd3_tc(
    const float* __restrict__ A,
    const unsigned* __restrict__ wiU,
    const float* __restrict__ bias,
    const float* __restrict__ lng, const float* __restrict__ lnb,
    int addres, float* __restrict__ Out) {
    extern __shared__ char smc[];
    unsigned sb = smem_u32(smc);
    int tid = threadIdx.x;
    int wid = tid >> 5, lane = tid & 31;
    int g = lane >> 2, tig = lane & 3;

    stageB(sb, wiU, tid, 256);
    cp_commit_wait();
    __syncthreads();

    int rowbase = blockIdx.x * 128 + wid * 16;
    int r0 = rowbase + g, r1 = rowbase + g + 8;
    int cr0 = (r0 < NN) ? r0 : (NN - 1);
    int cr1 = (r1 < NN) ? r1 : (NN - 1);

    float acc[16][4];
#pragma unroll
    for (int i = 0; i < 16; i++)
#pragma unroll
        for (int j = 0; j < 4; j++) acc[i][j] = 0.0f;

#pragma unroll
    for (int ks = 0; ks < 8; ks++) {
        int k0 = ks * 16;
        unsigned ahi[4], alo[4];
        loadA_frag(A, cr0, cr1, k0, tig, ahi, alo);
        mma3_tiles(acc, smc, k0, g, tig, ahi, alo);
    }

    float s0 = 0.f, sq0 = 0.f, s1 = 0.f, sq1 = 0.f;
#pragma unroll
    for (int t = 0; t < 16; t++) {
        int col = t * 8 + tig * 2;
        float2 bv = *(const float2*)&bias[col];
        acc[t][0] += bv.x; acc[t][1] += bv.y;
        acc[t][2] += bv.x; acc[t][3] += bv.y;
        s0 += acc[t][0] + acc[t][1];
        sq0 += acc[t][0] * acc[t][0] + acc[t][1] * acc[t][1];
        s1 += acc[t][2] + acc[t][3];
        sq1 += acc[t][2] * acc[t][2] + acc[t][3] * acc[t][3];
    }
#pragma unroll
    for (int off = 1; off <= 2; off <<= 1) {
        s0 += __shfl_xor_sync(0xffffffffu, s0, off);
        sq0 += __shfl_xor_sync(0xffffffffu, sq0, off);
        s1 += __shfl_xor_sync(0xffffffffu, s1, off);
        sq1 += __shfl_xor_sync(0xffffffffu, sq1, off);
    }
    float mu0 = s0 * (1.0f / HD);
    float mu1 = s1 * (1.0f / HD);
    float rstd0 = rsqrtf(sq0 * (1.0f / HD) - mu0 * mu0 + 1e-5f);
    float rstd1 = rsqrtf(sq1 * (1.0f / HD) - mu1 * mu1 + 1e-5f);

#pragma unroll
    for (int t = 0; t < 16; t++) {
        int col = t * 8 + tig * 2;
        float2 gv = *(const float2*)&lng[col];
        float2 lv = *(const float2*)&lnb[col];
        float2 v0, v1;
        v0.x = fmaxf((acc[t][0] - mu0) * rstd0 * gv.x + lv.x, 0.0f);
        v0.y = fmaxf((acc[t][1] - mu0) * rstd0 * gv.y + lv.y, 0.0f);
        v1.x = fmaxf((acc[t][2] - mu1) * rstd1 * gv.x + lv.x, 0.0f);
        v1.y = fmaxf((acc[t][3] - mu1) * rstd1 * gv.y + lv.y, 0.0f);
        if (r0 < NN) {
            if (addres) {
                float2 hv = *(const float2*)(Out + r0 * HD + col);
                v0.x += hv.x; v0.y += hv.y;
            }
            *(float2*)(Out + r0 * HD + col) = v0;
        }
        if (r1 < NN) {
            if (addres) {
                float2 hv = *(const float2*)(Out + r1 * HD + col);
                v1.x += hv.x; v1.y += hv.y;
            }
            *(float2*)(Out + r1 * HD + col) = v1;
        }
    }
}

// ---------------- weight transpose + split + interleave -------------------------
__device__ __forceinline__ void split_store(unsigned* __restrict__ dst,
                                            int m, int n, int kw,
                                            float v0, float v1) {
    __nv_bfloat16 h0 = __float2bfloat16(v0), h1 = __float2bfloat16(v1);
    __nv_bfloat16 l0 = __float2bfloat16(v0 - __bfloat162float(h0));
    __nv_bfloat16 l1 = __float2bfloat16(v1 - __bfloat162float(h1));
    dst[m * 16384 + n * 128 + kw * 2] =
        ((unsigned)__bfloat16_as_ushort(h1) << 16) | __bfloat16_as_ushort(h0);
    dst[m * 16384 + n * 128 + kw * 2 + 1] =
        ((unsigned)__bfloat16_as_ushort(l1) << 16) | __bfloat16_as_ushort(l0);
}

__global__ void split_msg(const float* __restrict__ msg_w1, unsigned* __restrict__ wi) {
    int n = blockIdx.x, m = blockIdx.y, kw = threadIdx.x;
    int l = m >> 1, part = m & 1;
    const float* W = msg_w1 + l * 257 * HD + part * 128 * HD;
    split_store(wi, m, n, kw, W[(2 * kw) * HD + n], W[(2 * kw + 1) * HD + n]);
}

__global__ void split_upd(const float* __restrict__ upd_w1,
                          const float* __restrict__ W2U,
                          const float* __restrict__ upd_w2,
                          unsigned* __restrict__ wi) {
    int n = blockIdx.x, m2 = blockIdx.y, kw = threadIdx.x;
    const float* W;
    if (m2 < 4)       W = upd_w1 + m2 * 256 * HD;
    else if (m2 < 8)  W = W2U + (m2 - 4) * HD * HD;
    else              W = upd_w2 + (m2 - 8) * HD * HD;
    split_store(wi, 8 + m2, n, kw, W[(2 * kw) * HD + n], W[(2 * kw + 1) * HD + n]);
}

// ---------------- tiny utility kernels ------------------------------------------
__global__ void zero_k(float* __restrict__ p, int n) {
    int i = blockIdx.x * blockDim.x + threadIdx.x;
    if (i < n) p[i] = 0.0f;
}
__global__ void zero_int(int* __restrict__ p, int n) {
    int i = blockIdx.x * blockDim.x + threadIdx.x;
    if (i < n) p[i] = 0;
}

// ---------------- CSR build ------------------------------------------------------
__global__ void count_k(const int* __restrict__ ei, int* __restrict__ deg) {
    int e = blockIdx.x * blockDim.x + threadIdx.x;
    if (e < EE) atomicAdd(&deg[ei[EE + e]], 1);
}

__global__ void scan_part(const int* __restrict__ deg, int* __restrict__ rowptr,
                          int* __restrict__ bsum) {
    __shared__ int s[256];
    int tid = threadIdx.x;
    int i = blockIdx.x * 256 + tid;
    int v = (i < NN) ? deg[i] : 0;
    s[tid] = v;
    __syncthreads();
#pragma unroll
    for (int off = 1; off < 256; off <<= 1) {
        int t = (tid >= off) ? s[tid - off] : 0;
        __syncthreads();
        s[tid] += t;
        __syncthreads();
    }
    if (i < NN) rowptr[i] = s[tid] - v;
    if (tid == 255) bsum[blockIdx.x] = s[255];
}

__global__ void scan_bsum(int* __restrict__ bsum) {
    __shared__ int s[256];
    int tid = threadIdx.x;
    int v = (tid < NB) ? bsum[tid] : 0;
    s[tid] = v;
    __syncthreads();
#pragma unroll
    for (int off = 1; off < 256; off <<= 1) {
        int t = (tid >= off) ? s[tid - off] : 0;
        __syncthreads();
        s[tid] += t;
        __syncthreads();
    }
    if (tid < NB) bsum[tid] = s[tid] - v;
}

__global__ void add_off(int* __restrict__ rowptr, const int* __restrict__ bsum,
                        int* __restrict__ cursor) {
    int i = blockIdx.x * 256 + threadIdx.x;
    if (i < NN) {
        int r = rowptr[i] + bsum[blockIdx.x];
        rowptr[i] = r;
        cursor[i] = r;
    }
    if (i == 0) rowptr[NN] = EE;
}

__global__ void degf_k(const int* __restrict__ rowptr, float* __restrict__ degf) {
    int i = blockIdx.x * blockDim.x + threadIdx.x;
    if (i < NN) degf[i] = (float)(rowptr[i + 1] - rowptr[i]);
}

__global__ void scatter_k(const int* __restrict__ ei,
                          const float* __restrict__ pos,
                          int* __restrict__ cursor,
                          int2* __restrict__ epack) {
    int e = blockIdx.x * blockDim.x + threadIdx.x;
    if (e >= EE) return;
    int s = ei[e];
    int t = ei[EE + e];
    float dx = pos[t * 3 + 0] - pos[s * 3 + 0];
    float dy = pos[t * 3 + 1] - pos[s * 3 + 1];
    float dz = pos[t * 3 + 2] - pos[s * 3 + 2];
    float dd = sqrtf(dx * dx + dy * dy + dz * dz);
    int p = atomicAdd(&cursor[t], 1);
    epack[p] = make_int2(s, __float_as_int(dd));
}

// ---------------- encoder --------------------------------------------------------
__global__ void encoder_k(const float* __restrict__ x,
                          const float* __restrict__ w,
                          const float* __restrict__ b,
                          float* __restrict__ h) {
    __shared__ float ws[15 * HD];
    __shared__ float xs[16 * 15];
    __shared__ float bs[HD];
    int c = threadIdx.x;
    for (int i = c; i < 15 * HD; i += HD) ws[i] = w[i];
    bs[c] = b[c];
    int n0 = blockIdx.x * 16;
    for (int i = c; i < 16 * 15; i += HD) {
        int nn = i / 15, kk = i % 15;
        int g = n0 + nn;
        xs[i] = (g < NN) ? x[g * 15 + kk] : 0.0f;
    }
    __syncthreads();
    for (int r = 0; r < 16; r++) {
        int g = n0 + r;
        if (g >= NN) break;
        float acc = bs[c];
#pragma unroll
        for (int k = 0; k < 15; k++) acc += xs[r * 15 + k] * ws[k * HD + c];
        h[g * HD + c] = acc;
    }
}

__global__ void build_w2u(const float* __restrict__ msg_w2,
                          const float* __restrict__ msg_b2,
                          const float* __restrict__ upd_w1,
                          float* __restrict__ W2U,
                          float* __restrict__ cvec) {
    int l = blockIdx.y, k = blockIdx.x, c = threadIdx.x;
    const float* u1b = upd_w1 + l * 256 * HD + 128 * HD;
    if (k < HD) {
        const float* wrow = msg_w2 + (l * HD + k) * HD;
        float acc = 0.0f;
        for (int j = 0; j < HD; j++) acc += wrow[j] * u1b[j * HD + c];
        W2U[(l * HD + k) * HD + c] = acc;
    } else {
        const float* brow = msg_b2 + l * HD;
        float acc = 0.0f;
        for (int j = 0; j < HD; j++) acc += brow[j] * u1b[j * HD + c];
        cvec[l * HD + c] = acc;
    }
}

// ---------------- CSR gather aggregation (bf16 P2) ------------------------------
__global__ void __launch_bounds__(256) aggregate_k(
    const int* __restrict__ rowptr,
    const int2* __restrict__ epack,
    const float* __restrict__ P1,
    const unsigned* __restrict__ P2b,
    const float* __restrict__ w1c,
    float* __restrict__ Yagg) {
    int node = blockIdx.x * 8 + (threadIdx.x >> 5);
    int lane = threadIdx.x & 31;
    int c4 = lane * 4;
    const float4 cw = *(const float4*)&w1c[c4];
    const float4 p1 = *(const float4*)&P1[node * HD + c4];
    float a0 = 0.f, a1 = 0.f, a2 = 0.f, a3 = 0.f;
    float b0 = 0.f, b1 = 0.f, b2 = 0.f, b3 = 0.f;
    float c0 = 0.f, c1 = 0.f, c2 = 0.f, c3 = 0.f;
    float d0 = 0.f, d1 = 0.f, d2 = 0.f, d3 = 0.f;
    int beg = rowptr[node], end = rowptr[node + 1];
    int e = beg;
    int w2 = lane * 2;   // P2b word index base
    for (; e + 3 < end; e += 4) {
        int2 q0 = epack[e], q1 = epack[e + 1], q2 = epack[e + 2], q3 = epack[e + 3];
        const uint2 u0 = *(const uint2*)&P2b[q0.x * 64 + w2];
        const uint2 u1 = *(const uint2*)&P2b[q1.x * 64 + w2];
        const uint2 u2 = *(const uint2*)&P2b[q2.x * 64 + w2];
        const uint2 u3 = *(const uint2*)&P2b[q3.x * 64 + w2];
        float dd0 = __int_as_float(q0.y), dd1 = __int_as_float(q1.y);
        float dd2 = __int_as_float(q2.y), dd3 = __int_as_float(q3.y);
        a0 += fmaxf(p1.x + __uint_as_float(u0.x << 16) + dd0 * cw.x, 0.0f);
        a1 += fmaxf(p1.y + __uint_as_float(u0.x & 0xFFFF0000u) + dd0 * cw.y, 0.0f);
        a2 += fmaxf(p1.z + __uint_as_float(u0.y << 16) + dd0 * cw.z, 0.0f);
        a3 += fmaxf(p1.w + __uint_as_float(u0.y & 0xFFFF0000u) + dd0 * cw.w, 0.0f);
        b0 += fmaxf(p1.x + __uint_as_float(u1.x << 16) + dd1 * cw.x, 0.0f);
        b1 += fmaxf(p1.y + __uint_as_float(u1.x & 0xFFFF0000u) + dd1 * cw.y, 0.0f);
        b2 += fmaxf(p1.z + __uint_as_float(u1.y << 16) + dd1 * cw.z, 0.0f);
        b3 += fmaxf(p1.w + __uint_as_float(u1.y & 0xFFFF0000u) + dd1 * cw.w, 0.0f);
        c0 += fmaxf(p1.x + __uint_as_float(u2.x << 16) + dd2 * cw.x, 0.0f);
        c1 += fmaxf(p1.y + __uint_as_float(u2.x & 0xFFFF0000u) + dd2 * cw.y, 0.0f);
        c2 += fmaxf(p1.z + __uint_as_float(u2.y << 16) + dd2 * cw.z, 0.0f);
        c3 += fmaxf(p1.w + __uint_as_float(u2.y & 0xFFFF0000u) + dd2 * cw.w, 0.0f);
        d0 += fmaxf(p1.x + __uint_as_float(u3.x << 16) + dd3 * cw.x, 0.0f);
        d1 += fmaxf(p1.y + __uint_as_float(u3.x & 0xFFFF0000u) + dd3 * cw.y, 0.0f);
        d2 += fmaxf(p1.z + __uint_as_float(u3.y << 16) + dd3 * cw.z, 0.0f);
        d3 += fmaxf(p1.w + __uint_as_float(u3.y & 0xFFFF0000u) + dd3 * cw.w, 0.0f);
    }
    for (; e < end; e++) {
        int2 q0 = epack[e];
        const uint2 u0 = *(const uint2*)&P2b[q0.x * 64 + w2];
        float dd0 = __int_as_float(q0.y);
        a0 += fmaxf(p1.x + __uint_as_float(u0.x << 16) + dd0 * cw.x, 0.0f);
        a1 += fmaxf(p1.y + __uint_as_float(u0.x & 0xFFFF0000u) + dd0 * cw.y, 0.0f);
        a2 += fmaxf(p1.z + __uint_as_float(u0.y << 16) + dd0 * cw.z, 0.0f);
        a3 += fmaxf(p1.w + __uint_as_float(u0.y & 0xFFFF0000u) + dd0 * cw.w, 0.0f);
    }
    *(float4*)&Yagg[node * HD + c4] = make_float4(
        (a0 + b0) + (c0 + d0), (a1 + b1) + (c1 + d1),
        (a2 + b2) + (c2 + d2), (a3 + b3) + (c3 + d3));
}

// ---------------- readout --------------------------------------------------------
__global__ void pool_k(const float* __restrict__ h,
                       const int* __restrict__ batch,
                       float* __restrict__ pooled, float* __restrict__ cnt) {
    int nidx = blockIdx.x * 8 + (threadIdx.x >> 5);
    int lane = threadIdx.x & 31;
    if (nidx >= NN) return;
    int g = batch[nidx];
    float4 v = *(const float4*)&h[nidx * HD + lane * 4];
    float* p = &pooled[g * HD + lane * 4];
    atomicAdd(p + 0, v.x);
    atomicAdd(p + 1, v.y);
    atomicAdd(p + 2, v.z);
    atomicAdd(p + 3, v.w);
    if (lane == 0) atomicAdd(&cnt[g], 1.0f);
}

__global__ void readout_k(const float* __restrict__ pooled,
                          const float* __restrict__ cnt,
                          const float* __restrict__ w1, const float* __restrict__ b1,
                          const float* __restrict__ w2, const float* __restrict__ b2,
                          const float* __restrict__ w3, const float* __restrict__ b3,
                          float* __restrict__ out) {
    __shared__ float p[HD];
    __shared__ float o1s[HD];
    __shared__ float o2s[64];
    int g = blockIdx.x, c = threadIdx.x;
    float cc = fmaxf(cnt[g], 1.0f);
    p[c] = pooled[g * HD + c] / cc;
    __syncthreads();
    float acc = b1[c];
    for (int k = 0; k < HD; k++) acc += p[k] * w1[k * HD + c];
    o1s[c] = fmaxf(acc, 0.0f);
    __syncthreads();
    if (c < 64) {
        float a = b2[c];
        for (int k = 0; k < HD; k++) a += o1s[k] * w2[k * 64 + c];
        o2s[c] = fmaxf(a, 0.0f);
    }
    __syncthreads();
    if (c == 0) {
        float a = b3[0];
        for (int k = 0; k < 64; k++) a += o2s[k] * w3[k];
        out[g] = a;
    }
}

// ---------------- launch ----------------------------------------------------------
extern "C" void kernel_launch(void* const* d_in, const int* in_sizes, int n_in,
                              void* d_out, int out_size) {
    const float* x       = (const float*)d_in[0];
    const int*   ei      = (const int*)d_in[1];
    const float* pos     = (const float*)d_in[3];
    const int*   batch   = (const int*)d_in[4];
    const float* enc_w   = (const float*)d_in[5];
    const float* enc_b   = (const float*)d_in[6];
    const float* msg_w1  = (const float*)d_in[9];
    const float* msg_b1  = (const float*)d_in[10];
    const float* msg_w2  = (const float*)d_in[11];
    const float* msg_b2  = (const float*)d_in[12];
    const float* upd_w1  = (const float*)d_in[13];
    const float* upd_b1  = (const float*)d_in[14];
    const float* upd_w2  = (const float*)d_in[15];
    const float* upd_b2  = (const float*)d_in[16];
    const float* ln_g    = (const float*)d_in[17];
    const float* ln_b    = (const float*)d_in[18];
    const float* mlp_w1  = (const float*)d_in[19];
    const float* mlp_b1  = (const float*)d_in[20];
    const float* mlp_w2  = (const float*)d_in[21];
    const float* mlp_b2  = (const float*)d_in[22];
    const float* mlp_w3  = (const float*)d_in[23];
    const float* mlp_b3  = (const float*)d_in[24];
    float*       out     = (float*)d_out;

    float *h, *P1, *Yagg, *T, *degf, *W2U, *cvec, *pooled, *cnt;
    int *rowptr, *cursor, *bsum;
    int2 *epack;
    unsigned *wi, *P2b;
    cudaGetSymbolAddress((void**)&h, d_h);
    cudaGetSymbolAddress((void**)&P1, d_P1);
    cudaGetSymbolAddress((void**)&P2b, d_P2b);
    cudaGetSymbolAddress((void**)&Yagg, d_Yagg);
    cudaGetSymbolAddress((void**)&T, d_T);
    cudaGetSymbolAddress((void**)&degf, d_degf);
    cudaGetSymbolAddress((void**)&W2U, d_W2U);
    cudaGetSymbolAddress((void**)&cvec, d_cvec);
    cudaGetSymbolAddress((void**)&pooled, d_pooled);
    cudaGetSymbolAddress((void**)&cnt, d_cnt);
    cudaGetSymbolAddress((void**)&rowptr, d_rowptr);
    cudaGetSymbolAddress((void**)&cursor, d_cursor);
    cudaGetSymbolAddress((void**)&bsum, d_bsum);
    cudaGetSymbolAddress((void**)&epack, d_epack);
    cudaGetSymbolAddress((void**)&wi, d_wi);

    cudaFuncSetAttribute(p12_tc,  cudaFuncAttributeMaxDynamicSharedMemorySize, BTILE);
    cudaFuncSetAttribute(upd2_tc, cudaFuncAttributeMaxDynamicSharedMemorySize, BTILE);
    cudaFuncSetAttribute(upd3_tc, cudaFuncAttributeMaxDynamicSharedMemorySize, BTILE);

    // ---- prep; launch #4 = layer-0 p12 so ncu captures it ----
    encoder_k<<<(NN + 15) / 16, 128>>>(x, enc_w, enc_b, h);               // 1
    split_msg<<<dim3(128, 8), 64>>>(msg_w1, wi);                          // 2
    zero_int<<<(NN + 255) / 256, 256>>>(cursor, NN);                      // 3
    p12_tc<<<2 * G128, 256, BTILE>>>(h, wi, msg_b1, P1, P2b);             // 4 (profiled)
    count_k<<<(EE + 255) / 256, 256>>>(ei, cursor);                       // 5
    scan_part<<<NB, 256>>>(cursor, rowptr, bsum);                         // 6
    scan_bsum<<<1, 256>>>(bsum);                                          // 7
    add_off<<<NB, 256>>>(rowptr, bsum, cursor);                           // 8
    degf_k<<<(NN + 255) / 256, 256>>>(rowptr, degf);                      // 9
    scatter_k<<<(EE + 255) / 256, 256>>>(ei, pos, cursor, epack);         // 10
    build_w2u<<<dim3(129, 4), 128>>>(msg_w2, msg_b2, upd_w1, W2U, cvec);  // 11
    split_upd<<<dim3(128, 12), 64>>>(upd_w1, W2U, upd_w2, wi);            // 12
    zero_k<<<(NG * HD + 255) / 256, 256>>>(pooled, NG * HD);              // 13
    zero_k<<<1, 64>>>(cnt, NG);                                           // 14

    for (int l = 0; l < NLAY; l++) {
        const float* w1l = msg_w1 + l * 257 * HD;
        if (l > 0) {
            p12_tc<<<2 * G128, 256, BTILE>>>(h, wi + (2 * l) * 16384,
                                             msg_b1 + l * HD, P1, P2b);
        }
        aggregate_k<<<NN / 8, 256>>>(rowptr, epack, P1, P2b,
                                     w1l + 256 * HD, Yagg);
        upd2_tc<<<G128, 256, BTILE>>>(h, Yagg,
                                      wi + (8 + l) * 16384, wi + (12 + l) * 16384,
                                      upd_b1 + l * HD, degf, cvec + l * HD, T);
        upd3_tc<<<G128, 256, BTILE>>>(T, wi + (16 + l) * 16384,
                                      upd_b2 + l * HD, ln_g + l * HD, ln_b + l * HD,
                                      (l > 0) ? 1 : 0, h);
    }

    pool_k<<<(NN + 7) / 8, 256>>>(h, batch, pooled, cnt);
    readout_k<<<NG, 128>>>(pooled, cnt, mlp_w1, mlp_b1, mlp_w2, mlp_b2,
                           mlp_w3, mlp_b3, out);
}